// round 4
// baseline (speedup 1.0000x reference)
#include <cuda_runtime.h>
#include <cuda_bf16.h>

// Problem constants
#define B_   32
#define T_   4
#define D_   2048
#define H_   16
#define G_   4
#define K_   128
#define S_   4096
#define NREP 4
#define SCALE_ 0.08838834764831845f   // K^-0.5
#define EPS_   1e-6f

// ---------------- device scratch (no allocations allowed) ----------------
__device__ float g_qkv[128 * 3072];       // raw projections [m=b*T+t][3072]
__device__ float g_q  [128 * H_ * K_];    // post norm+rope  [m][h][k]
__device__ float g_kn [128 * G_ * K_];    // new K rows      [m][g][k]
__device__ float g_vn [128 * G_ * K_];    // new V rows      [m][g][k]
__device__ float g_attn[128 * H_ * K_];   // attention out   [m][h][k]
__device__ int   g_pos[128];              // rope position per (b,t)
__device__ int   g_start[B_];             // left pads per b

// ---------------- K0: positions / left pads ----------------
__global__ void pos_kernel(const int* __restrict__ seg, const int* __restrict__ curp) {
    int b = threadIdx.x;
    if (b >= B_) return;
    int cur = *curp;
    int c = 0, lp = 0;
    for (int t = 0; t < T_; t++) {
        int v = (seg[b * T_ + t] != 0) ? 1 : 0;
        c += v;
        if (c == 0) lp++;
        g_pos[b * T_ + t] = c - 1 + cur;
    }
    g_start[b] = lp;
}

// ---------------- K1/K4: tiled fp32 GEMM, M=128, Kdim=2048 ----------------
// mode 0: C = g_qkv (ldc=3072), A = Ain(hidden), cols select Wq/Wk/Wv
// mode 1: C = Cout  (ldc=2048), A = g_attn, W0 = Wo
__global__ void gemm128_kernel(const float* __restrict__ Ain,
                               const float* __restrict__ W0,
                               const float* __restrict__ W1,
                               const float* __restrict__ W2,
                               float* __restrict__ Cout,
                               int ldc, int mode)
{
    __shared__ float As[32][33];   // [k][m], padded
    __shared__ float Bs[32][64];   // [k][n]

    const float* A = (mode == 0) ? Ain : g_attn;
    float* C = (mode == 0) ? g_qkv : Cout;

    int c0 = blockIdx.x * 64;
    const float* W; int ldb; int cb;
    if (c0 < 2048)      { W = W0; ldb = 2048; cb = c0; }
    else if (c0 < 2560) { W = W1; ldb = 512;  cb = c0 - 2048; }
    else                { W = W2; ldb = 512;  cb = c0 - 2560; }

    int m0  = blockIdx.y * 32;
    int tid = threadIdx.x;          // 256 threads
    int tx  = tid & 15;             // 16 cols of 4
    int ty  = tid >> 4;             // 16 rows of 2

    float acc0[4] = {0.f,0.f,0.f,0.f};
    float acc1[4] = {0.f,0.f,0.f,0.f};

    int am = tid >> 3;              // A row 0..31
    int ak = (tid & 7) << 2;        // A col quad

    for (int k0 = 0; k0 < 2048; k0 += 32) {
        float4 av = *(const float4*)(A + (size_t)(m0 + am) * 2048 + k0 + ak);
        As[ak + 0][am] = av.x; As[ak + 1][am] = av.y;
        As[ak + 2][am] = av.z; As[ak + 3][am] = av.w;
        #pragma unroll
        for (int r = 0; r < 2; r++) {
            int idx = tid + (r << 8);     // 0..511
            int kr  = idx >> 4;           // 0..31
            int nq  = (idx & 15) << 2;    // 0..60
            float4 bv = *(const float4*)(W + (size_t)(k0 + kr) * ldb + cb + nq);
            *(float4*)&Bs[kr][nq] = bv;
        }
        __syncthreads();
        #pragma unroll
        for (int kk = 0; kk < 32; kk++) {
            float a0 = As[kk][ty * 2 + 0];
            float a1 = As[kk][ty * 2 + 1];
            float4 bv = *(const float4*)&Bs[kk][tx << 2];
            acc0[0] = fmaf(a0, bv.x, acc0[0]);
            acc0[1] = fmaf(a0, bv.y, acc0[1]);
            acc0[2] = fmaf(a0, bv.z, acc0[2]);
            acc0[3] = fmaf(a0, bv.w, acc0[3]);
            acc1[0] = fmaf(a1, bv.x, acc1[0]);
            acc1[1] = fmaf(a1, bv.y, acc1[1]);
            acc1[2] = fmaf(a1, bv.z, acc1[2]);
            acc1[3] = fmaf(a1, bv.w, acc1[3]);
        }
        __syncthreads();
    }

    float* cp0 = C + (size_t)(m0 + ty * 2) * ldc + c0 + (tx << 2);
    float* cp1 = cp0 + ldc;
    *(float4*)cp0 = make_float4(acc0[0], acc0[1], acc0[2], acc0[3]);
    *(float4*)cp1 = make_float4(acc1[0], acc1[1], acc1[2], acc1[3]);
}

// ---------------- K2: rmsnorm + rope + split ----------------
// grid (24 slots, 128 rows), 128 threads. slots: 0..15 q heads, 16..19 k, 20..23 v
__global__ void normrope_kernel(const float* __restrict__ q_scale,
                                const float* __restrict__ k_scale)
{
    int slot = blockIdx.x;
    int m    = blockIdx.y;
    int tid  = threadIdx.x;

    int cbase, type, gi = 0;
    if (slot < 16)      { cbase = slot * 128;               type = 0; }
    else if (slot < 20) { cbase = 2048 + (slot - 16) * 128; type = 1; gi = slot - 16; }
    else                { cbase = 2560 + (slot - 20) * 128; type = 2; gi = slot - 20; }

    float x = g_qkv[m * 3072 + cbase + tid];

    if (type == 2) {   // V: no norm, no rope
        g_vn[(m * G_ + gi) * K_ + tid] = x;
        return;
    }

    __shared__ float wsum[4];
    __shared__ float sx[128];

    float ss = x * x;
    #pragma unroll
    for (int o = 16; o; o >>= 1) ss += __shfl_xor_sync(0xffffffffu, ss, o);
    if ((tid & 31) == 0) wsum[tid >> 5] = ss;
    __syncthreads();
    float var = (wsum[0] + wsum[1] + wsum[2] + wsum[3]) * (1.0f / 128.0f);

    float sc = (type == 0) ? q_scale[tid] : k_scale[tid];
    float xn = x * rsqrtf(var + EPS_) * sc;
    sx[tid] = xn;
    __syncthreads();

    int   pos = g_pos[m];
    int   j   = tid & 63;
    float fr  = (float)j * (1.0f / 64.0f);
    float ts  = powf(10000.0f, fr);        // accurate pow (precision matters: large angles)
    float ang = (float)pos / ts;
    float sv, cv;
    sincosf(ang, &sv, &cv);

    float out = (tid < 64) ? (sx[j] * cv - sx[j + 64] * sv)
                           : (sx[j + 64] * cv + sx[j] * sv);

    if (type == 0) g_q [(m * H_ + slot) * K_ + tid] = out;
    else           g_kn[(m * G_ + gi)  * K_ + tid] = out;
}

// ---------------- K3: flash attention, one block per (b,g) ----------------
// dyn smem layout (floats): QS[16*128] | KS[64*132] | VS[64*132] | P[16*65] | M[16] L[16] F[16]
#define ATTN_SMEM_BYTES ((2048 + 8448 + 8448 + 1040 + 48) * 4)

__global__ void attn_kernel(const float* __restrict__ kc,
                            const float* __restrict__ vc,
                            const int*   __restrict__ seg,
                            const int*   __restrict__ curp)
{
    extern __shared__ float smf[];
    float* QS   = smf;
    float* KS   = smf + 2048;
    float* VS   = smf + 2048 + 8448;
    float* P    = smf + 2048 + 16896;
    float* SM_M = P + 1040;
    float* SM_L = SM_M + 16;
    float* SM_F = SM_L + 16;

    int b = blockIdx.x;
    int g = blockIdx.y;
    int tid  = threadIdx.x;            // 256
    int w    = tid >> 5;
    int lane = tid & 31;

    int cur   = *curp;
    int start = g_start[b];
    int s_end = cur + T_;

    // load the 16 query vectors for this (b,g)
    #pragma unroll
    for (int it = 0; it < 2; it++) {
        int idx = tid + (it << 8);     // 0..511 float4 units
        int q   = idx >> 5;
        int c4  = (idx & 31) << 2;
        int t = q >> 2, r = q & 3;
        float4 qv = *(const float4*)(g_q + (((b * T_ + t) * H_ + (g * NREP + r)) << 7) + c4);
        *(float4*)(QS + q * 128 + c4) = qv;
    }
    if (tid < 16) { SM_M[tid] = -3e38f; SM_L[tid] = 0.f; }

    float a00=0,a01=0,a02=0,a03=0, a10=0,a11=0,a12=0,a13=0;
    int qp = w;                         // this warp's query pair {2w, 2w+1} for softmax/PV
    int sl = ((w & 1) << 5) + lane;     // logits: this lane's s row within chunk
    int qb = (w >> 1) << 2;             // logits: 4-query group

    __syncthreads();

    for (int s0 = 0; s0 < s_end; s0 += 64) {
        // ---- load K/V chunk (coalesced; new rows from scratch) ----
        #pragma unroll
        for (int it = 0; it < 8; it++) {
            int idx = tid + (it << 8);
            int row = idx >> 5;
            int c4  = (idx & 31) << 2;
            int s   = s0 + row;
            float4 kv = make_float4(0.f,0.f,0.f,0.f);
            float4 vv = kv;
            if (s < cur) {
                size_t off = (((size_t)(b * S_ + s)) * G_ + g) * K_ + c4;
                kv = *(const float4*)(kc + off);
                vv = *(const float4*)(vc + off);
            } else if (s < s_end) {
                int off = (((b * T_ + (s - cur)) * G_ + g) << 7) + c4;
                kv = *(const float4*)(g_kn + off);
                vv = *(const float4*)(g_vn + off);
            }
            *(float4*)(KS + row * 132 + c4) = kv;
            *(float4*)(VS + row * 132 + c4) = vv;
        }
        __syncthreads();

        // ---- logits: warp computes 4 queries x its 32 s-rows ----
        {
            const float* krow = KS + sl * 132;
            const float* q0 = QS + qb * 128;
            const float* q1 = q0 + 128;
            const float* q2 = q1 + 128;
            const float* q3 = q2 + 128;
            float l0=0.f,l1=0.f,l2=0.f,l3=0.f;
            #pragma unroll
            for (int kk = 0; kk < 128; kk += 4) {
                float4 kv = *(const float4*)(krow + kk);
                float4 a;
                a = *(const float4*)(q0 + kk);
                l0 = fmaf(a.x,kv.x,l0); l0 = fmaf(a.y,kv.y,l0);
                l0 = fmaf(a.z,kv.z,l0); l0 = fmaf(a.w,kv.w,l0);
                a = *(const float4*)(q1 + kk);
                l1 = fmaf(a.x,kv.x,l1); l1 = fmaf(a.y,kv.y,l1);
                l1 = fmaf(a.z,kv.z,l1); l1 = fmaf(a.w,kv.w,l1);
                a = *(const float4*)(q2 + kk);
                l2 = fmaf(a.x,kv.x,l2); l2 = fmaf(a.y,kv.y,l2);
                l2 = fmaf(a.z,kv.z,l2); l2 = fmaf(a.w,kv.w,l2);
                a = *(const float4*)(q3 + kk);
                l3 = fmaf(a.x,kv.x,l3); l3 = fmaf(a.y,kv.y,l3);
                l3 = fmaf(a.z,kv.z,l3); l3 = fmaf(a.w,kv.w,l3);
            }
            int s   = s0 + sl;
            int kvv = (s >= start && s < s_end) ? 1 : 0;
            float lv[4] = {l0, l1, l2, l3};
            #pragma unroll
            for (int j = 0; j < 4; j++) {
                int q = qb + j;
                int t = q >> 2;
                bool ok = (s <= cur + t) && (kvv == seg[b * T_ + t]);
                P[q * 65 + sl] = ok ? lv[j] * SCALE_ : -3e38f;
            }
        }
        __syncthreads();

        // ---- online softmax: warp w owns queries {2w, 2w+1} ----
        #pragma unroll
        for (int j = 0; j < 2; j++) {
            int q = (w << 1) + j;
            float v0 = P[q * 65 + lane];
            float v1 = P[q * 65 + lane + 32];
            float cm = fmaxf(v0, v1);
            #pragma unroll
            for (int o = 16; o; o >>= 1) cm = fmaxf(cm, __shfl_xor_sync(0xffffffffu, cm, o));
            float mold = SM_M[q];
            float mnew = fmaxf(mold, cm);
            float e0 = (v0 < -1e37f) ? 0.f : __expf(v0 - mnew);
            float e1 = (v1 < -1e37f) ? 0.f : __expf(v1 - mnew);
            P[q * 65 + lane]      = e0;
            P[q * 65 + lane + 32] = e1;
            float sum = e0 + e1;
            #pragma unroll
            for (int o = 16; o; o >>= 1) sum += __shfl_xor_sync(0xffffffffu, sum, o);
            if (lane == 0) {
                float f = (mold < -1e37f) ? 0.f : __expf(mold - mnew);
                SM_F[q] = f;
                SM_L[q] = SM_L[q] * f + sum;
                SM_M[q] = mnew;
            }
        }
        __syncthreads();

        // ---- PV: warp w accumulates its 2 queries, lane owns 4 dims ----
        {
            float f0 = SM_F[(qp << 1)];
            float f1 = SM_F[(qp << 1) + 1];
            a00*=f0; a01*=f0; a02*=f0; a03*=f0;
            a10*=f1; a11*=f1; a12*=f1; a13*=f1;
            const float* p0    = P + (qp << 1) * 65;
            const float* p1    = p0 + 65;
            const float* vbase = VS + (lane << 2);
            #pragma unroll 8
            for (int ssi = 0; ssi < 64; ssi++) {
                float w0 = p0[ssi], w1 = p1[ssi];
                float4 vv = *(const float4*)(vbase + ssi * 132);
                a00 = fmaf(w0, vv.x, a00); a01 = fmaf(w0, vv.y, a01);
                a02 = fmaf(w0, vv.z, a02); a03 = fmaf(w0, vv.w, a03);
                a10 = fmaf(w1, vv.x, a10); a11 = fmaf(w1, vv.y, a11);
                a12 = fmaf(w1, vv.z, a12); a13 = fmaf(w1, vv.w, a13);
            }
        }
        __syncthreads();
    }

    // ---- finalize ----
    {
        int q0i = qp << 1;
        int q1i = q0i + 1;
        float il0 = 1.0f / SM_L[q0i];
        float il1 = 1.0f / SM_L[q1i];
        int t0 = q0i >> 2, r0 = q0i & 3;
        int t1 = q1i >> 2, r1 = q1i & 3;
        *(float4*)(g_attn + (((b * T_ + t0) * H_ + g * NREP + r0) << 7) + (lane << 2))
            = make_float4(a00 * il0, a01 * il0, a02 * il0, a03 * il0);
        *(float4*)(g_attn + (((b * T_ + t1) * H_ + g * NREP + r1) << 7) + (lane << 2))
            = make_float4(a10 * il1, a11 * il1, a12 * il1, a13 * il1);
    }
}

// ---------------- host launch ----------------
extern "C" void kernel_launch(void* const* d_in, const int* in_sizes, int n_in,
                              void* d_out, int out_size) {
    const float* hidden = (const float*)d_in[0];
    const int*   seg    = (const int*)  d_in[1];
    const float* kc     = (const float*)d_in[2];
    const float* vc     = (const float*)d_in[3];
    const float* Wq     = (const float*)d_in[4];
    const float* Wk     = (const float*)d_in[5];
    const float* Wv     = (const float*)d_in[6];
    const float* Wo     = (const float*)d_in[7];
    const float* qsc    = (const float*)d_in[8];
    const float* ksc    = (const float*)d_in[9];
    const int*   curp   = (const int*)  d_in[10];

    (void)in_sizes; (void)n_in; (void)out_size;

    pos_kernel<<<1, 32>>>(seg, curp);
    gemm128_kernel<<<dim3(48, 4), 256>>>(hidden, Wq, Wk, Wv, nullptr, 3072, 0);
    normrope_kernel<<<dim3(24, 128), 128>>>(qsc, ksc);
    cudaFuncSetAttribute(attn_kernel, cudaFuncAttributeMaxDynamicSharedMemorySize,
                         ATTN_SMEM_BYTES);
    attn_kernel<<<dim3(B_, G_), 256, ATTN_SMEM_BYTES>>>(kc, vc, seg, curp);
    gemm128_kernel<<<dim3(32, 4), 256>>>(nullptr, Wo, Wo, Wo, (float*)d_out, 2048, 1);
}

// round 9
// speedup vs baseline: 1.6108x; 1.6108x over previous
#include <cuda_runtime.h>
#include <cuda_bf16.h>
#include <stdint.h>
#include <stddef.h>

// Problem constants
#define B_   32
#define T_   4
#define D_   2048
#define H_   16
#define G_   4
#define K_   128
#define S_   4096
#define NREP 4
#define NS   4            // sequence splits for attention
#define SCALE_ 0.08838834764831845f   // K^-0.5
#define EPS_   1e-6f

// ---------------- device scratch (no allocations allowed) ----------------
__device__ __align__(16) float g_qkv[128 * 3072];       // raw projections
__device__ __align__(16) float g_q  [128 * H_ * K_];    // post norm+rope
__device__ __align__(16) float g_kn [128 * G_ * K_];    // new K rows
__device__ __align__(16) float g_vn [128 * G_ * K_];    // new V rows
__device__ __align__(16) float g_attn[128 * H_ * K_];   // attention out
__device__ int   g_pos[128];              // rope position per (b,t)
__device__ int   g_start[B_];             // left pads per b
// split-attention partials
__device__ __align__(16) float g_pacc[B_ * G_ * NS * 16 * 128];
__device__ float g_pm  [B_ * G_ * NS * 16];
__device__ float g_pl  [B_ * G_ * NS * 16];

// ---------------- K0: positions / left pads ----------------
__global__ void pos_kernel(const int* __restrict__ seg, const int* __restrict__ curp) {
    int b = threadIdx.x;
    if (b >= B_) return;
    int cur = *curp;
    int c = 0, lp = 0;
    for (int t = 0; t < T_; t++) {
        int v = (seg[b * T_ + t] != 0) ? 1 : 0;
        c += v;
        if (c == 0) lp++;
        g_pos[b * T_ + t] = c - 1 + cur;
    }
    g_start[b] = lp;
}

// ---------------- GEMM: 32x64 tile, 128 thr, 4x4 reg tile ----------------
// double-buffered smem, register prefetch (plain loads, no cp.async)
// qkv=1: C_==nullptr -> C = g_qkv (ldc=3072), A = hidden, cols select Wq/Wk/Wv
// qkv=0: C = Cout (ldc=2048), A_==nullptr -> A = g_attn, W0 = Wo
__global__ __launch_bounds__(128) void gemm_kernel(
    const float* __restrict__ A_,
    const float* __restrict__ W0, const float* __restrict__ W1,
    const float* __restrict__ W2,
    float* __restrict__ C_, int ldc, int qkv)
{
    __shared__ alignas(16) float As[2][32][33];   // [buf][k][m] padded
    __shared__ alignas(16) float Bs[2][32][68];   // [buf][k][n] padded

    const float* A = A_ ? A_ : (const float*)g_attn;
    float*       C = C_ ? C_ : (float*)g_qkv;     // <-- R4-R8 bug fix: was nullptr deref

    int c0 = blockIdx.x * 64;
    const float* W; int ldb, cb;
    if (qkv) {
        if (c0 < 2048)      { W = W0; ldb = 2048; cb = c0; }
        else if (c0 < 2560) { W = W1; ldb = 512;  cb = c0 - 2048; }
        else                { W = W2; ldb = 512;  cb = c0 - 2560; }
    } else                  { W = W0; ldb = 2048; cb = c0; }

    int m0  = blockIdx.y * 32;
    int tid = threadIdx.x;          // 128
    int tx  = tid & 15;             // 16 cols of 4
    int ty  = tid >> 4;             // 8 rows of 4

    // per-thread load coordinates (fixed)
    int am0 = tid >> 3;             // A: j=0 row
    int ak  = (tid & 7) << 2;       // A: k quad
    int br  = tid >> 4;             // B: j=0 row
    int bn  = (tid & 15) << 2;      // B: n quad

    float4 ra[2], rb[4];

    auto gload = [&](int it) {
        int k0 = it << 5;
        ra[0] = *(const float4*)(A + (size_t)(m0 + am0)      * 2048 + k0 + ak);
        ra[1] = *(const float4*)(A + (size_t)(m0 + am0 + 16) * 2048 + k0 + ak);
        #pragma unroll
        for (int j = 0; j < 4; j++)
            rb[j] = *(const float4*)(W + (size_t)(k0 + br + j * 8) * ldb + cb + bn);
    };
    auto sstore = [&](int buf) {
        #pragma unroll
        for (int j = 0; j < 2; j++) {
            int am = am0 + j * 16;
            As[buf][ak + 0][am] = ra[j].x;
            As[buf][ak + 1][am] = ra[j].y;
            As[buf][ak + 2][am] = ra[j].z;
            As[buf][ak + 3][am] = ra[j].w;
        }
        #pragma unroll
        for (int j = 0; j < 4; j++)
            *(float4*)&Bs[buf][br + j * 8][bn] = rb[j];
    };

    float acc[4][4];
    #pragma unroll
    for (int i = 0; i < 4; i++)
        #pragma unroll
        for (int j = 0; j < 4; j++) acc[i][j] = 0.f;

    gload(0);
    sstore(0);
    __syncthreads();

    for (int it = 0; it < 64; it++) {
        int bf = it & 1;
        if (it < 63) gload(it + 1);           // prefetch next tile into regs
        #pragma unroll
        for (int kk = 0; kk < 32; kk++) {
            float a0 = As[bf][kk][ty * 4 + 0];
            float a1 = As[bf][kk][ty * 4 + 1];
            float a2 = As[bf][kk][ty * 4 + 2];
            float a3 = As[bf][kk][ty * 4 + 3];
            float4 bv = *(const float4*)&Bs[bf][kk][tx << 2];
            acc[0][0] = fmaf(a0, bv.x, acc[0][0]);
            acc[0][1] = fmaf(a0, bv.y, acc[0][1]);
            acc[0][2] = fmaf(a0, bv.z, acc[0][2]);
            acc[0][3] = fmaf(a0, bv.w, acc[0][3]);
            acc[1][0] = fmaf(a1, bv.x, acc[1][0]);
            acc[1][1] = fmaf(a1, bv.y, acc[1][1]);
            acc[1][2] = fmaf(a1, bv.z, acc[1][2]);
            acc[1][3] = fmaf(a1, bv.w, acc[1][3]);
            acc[2][0] = fmaf(a2, bv.x, acc[2][0]);
            acc[2][1] = fmaf(a2, bv.y, acc[2][1]);
            acc[2][2] = fmaf(a2, bv.z, acc[2][2]);
            acc[2][3] = fmaf(a2, bv.w, acc[2][3]);
            acc[3][0] = fmaf(a3, bv.x, acc[3][0]);
            acc[3][1] = fmaf(a3, bv.y, acc[3][1]);
            acc[3][2] = fmaf(a3, bv.z, acc[3][2]);
            acc[3][3] = fmaf(a3, bv.w, acc[3][3]);
        }
        __syncthreads();                       // all reads of bf done
        if (it < 63) {
            sstore(bf ^ 1);                    // write next tile (other buffer)
            __syncthreads();                   // visible before next compute
        }
    }

    #pragma unroll
    for (int i = 0; i < 4; i++) {
        float* cp = C + (size_t)(m0 + ty * 4 + i) * ldc + c0 + (tx << 2);
        *(float4*)cp = make_float4(acc[i][0], acc[i][1], acc[i][2], acc[i][3]);
    }
}

// ---------------- K2: rmsnorm + rope + split ----------------
__global__ void normrope_kernel(const float* __restrict__ q_scale,
                                const float* __restrict__ k_scale)
{
    int slot = blockIdx.x;
    int m    = blockIdx.y;
    int tid  = threadIdx.x;

    int cbase, type, gi = 0;
    if (slot < 16)      { cbase = slot * 128;               type = 0; }
    else if (slot < 20) { cbase = 2048 + (slot - 16) * 128; type = 1; gi = slot - 16; }
    else                { cbase = 2560 + (slot - 20) * 128; type = 2; gi = slot - 20; }

    float x = g_qkv[m * 3072 + cbase + tid];

    if (type == 2) {   // V: no norm, no rope
        g_vn[(m * G_ + gi) * K_ + tid] = x;
        return;
    }

    __shared__ float wsum[4];
    __shared__ float sx[128];

    float ss = x * x;
    #pragma unroll
    for (int o = 16; o; o >>= 1) ss += __shfl_xor_sync(0xffffffffu, ss, o);
    if ((tid & 31) == 0) wsum[tid >> 5] = ss;
    __syncthreads();
    float var = (wsum[0] + wsum[1] + wsum[2] + wsum[3]) * (1.0f / 128.0f);

    float sc = (type == 0) ? q_scale[tid] : k_scale[tid];
    float xn = x * rsqrtf(var + EPS_) * sc;
    sx[tid] = xn;
    __syncthreads();

    int   pos = g_pos[m];
    int   j   = tid & 63;
    float fr  = (float)j * (1.0f / 64.0f);
    float ts  = powf(10000.0f, fr);        // accurate pow (large angles)
    float ang = (float)pos / ts;
    float sv, cv;
    sincosf(ang, &sv, &cv);

    float out = (tid < 64) ? (sx[j] * cv - sx[j + 64] * sv)
                           : (sx[j + 64] * cv + sx[j] * sv);

    if (type == 0) g_q [(m * H_ + slot) * K_ + tid] = out;
    else           g_kn[(m * G_ + gi)  * K_ + tid] = out;
}

// ---------------- K3: split flash attention (synchronous staging) ----------------
// dyn smem floats: QS[2048] | KS[64*132] | VS[64*132] | P[16*65] | M/L/F[48]
#define ATTN_SMEM_FLOATS (2048 + 8448 + 8448 + 1040 + 48)
#define ATTN_SMEM_BYTES  (ATTN_SMEM_FLOATS * 4)

__global__ __launch_bounds__(256) void attn_kernel(
    const float* __restrict__ kc,
    const float* __restrict__ vc,
    const int*   __restrict__ seg,
    const int*   __restrict__ curp)
{
    extern __shared__ float smf[];
    float* QS   = smf;
    float* KS   = smf + 2048;
    float* VS   = KS + 8448;
    float* P    = VS + 8448;
    float* SM_M = P + 1040;
    float* SM_L = SM_M + 16;
    float* SM_F = SM_L + 16;

    int b  = blockIdx.x;
    int g  = blockIdx.y;
    int sp = blockIdx.z;
    int tid  = threadIdx.x;            // 256
    int w    = tid >> 5;
    int lane = tid & 31;

    int cur   = *curp;
    int start = g_start[b];
    int s_end = cur + T_;

    int sgv0 = seg[b * T_ + 0], sgv1 = seg[b * T_ + 1];
    int sgv2 = seg[b * T_ + 2], sgv3 = seg[b * T_ + 3];

    // chunk range for this split
    int nch  = (s_end + 63) >> 6;
    int per  = (nch + NS - 1) / NS;
    int c_lo = sp * per;
    int c_hi = min(nch, c_lo + per);
    int cst  = max(c_lo, start >> 6);

    // load the 16 query vectors for this (b,g)
    #pragma unroll
    for (int it = 0; it < 2; it++) {
        int idx = tid + (it << 8);
        int q   = idx >> 5;
        int c4  = (idx & 31) << 2;
        int t = q >> 2, r = q & 3;
        float4 qv = *(const float4*)(g_q + (((b * T_ + t) * H_ + (g * NREP + r)) << 7) + c4);
        *(float4*)(QS + q * 128 + c4) = qv;
    }
    if (tid < 16) { SM_M[tid] = -3e38f; SM_L[tid] = 0.f; }

    float a00=0,a01=0,a02=0,a03=0, a10=0,a11=0,a12=0,a13=0;
    int sl = ((w & 1) << 5) + lane;     // logits: lane's s row within chunk
    int qb = (w >> 1) << 2;             // logits: 4-query group

    __syncthreads();

    for (int ci = cst; ci < c_hi; ci++) {
        int s0 = ci << 6;

        // ---- load K/V chunk (coalesced; new rows from scratch) ----
        #pragma unroll
        for (int it = 0; it < 8; it++) {
            int idx = tid + (it << 8);
            int row = idx >> 5;
            int c4  = (idx & 31) << 2;
            int s   = s0 + row;
            float4 kv = make_float4(0.f,0.f,0.f,0.f);
            float4 vv = kv;
            if (s < cur) {
                size_t off = (((size_t)(b * S_ + s)) * G_ + g) * K_ + c4;
                kv = *(const float4*)(kc + off);
                vv = *(const float4*)(vc + off);
            } else if (s < s_end) {
                int off = (((b * T_ + (s - cur)) * G_ + g) << 7) + c4;
                kv = *(const float4*)(g_kn + off);
                vv = *(const float4*)(g_vn + off);
            }
            *(float4*)(KS + row * 132 + c4) = kv;
            *(float4*)(VS + row * 132 + c4) = vv;
        }
        __syncthreads();

        // ---- logits: warp computes 4 queries x its 32 s-rows ----
        {
            const float* krow = KS + sl * 132;
            const float* q0 = QS + qb * 128;
            const float* q1 = q0 + 128;
            const float* q2 = q1 + 128;
            const float* q3 = q2 + 128;
            float l0=0.f,l1=0.f,l2=0.f,l3=0.f;
            #pragma unroll
            for (int kk = 0; kk < 128; kk += 4) {
                float4 kv = *(const float4*)(krow + kk);
                float4 a;
                a = *(const float4*)(q0 + kk);
                l0 = fmaf(a.x,kv.x,l0); l0 = fmaf(a.y,kv.y,l0);
                l0 = fmaf(a.z,kv.z,l0); l0 = fmaf(a.w,kv.w,l0);
                a = *(const float4*)(q1 + kk);
                l1 = fmaf(a.x,kv.x,l1); l1 = fmaf(a.y,kv.y,l1);
                l1 = fmaf(a.z,kv.z,l1); l1 = fmaf(a.w,kv.w,l1);
                a = *(const float4*)(q2 + kk);
                l2 = fmaf(a.x,kv.x,l2); l2 = fmaf(a.y,kv.y,l2);
                l2 = fmaf(a.z,kv.z,l2); l2 = fmaf(a.w,kv.w,l2);
                a = *(const float4*)(q3 + kk);
                l3 = fmaf(a.x,kv.x,l3); l3 = fmaf(a.y,kv.y,l3);
                l3 = fmaf(a.z,kv.z,l3); l3 = fmaf(a.w,kv.w,l3);
            }
            int s   = s0 + sl;
            int kvv = (s >= start && s < s_end) ? 1 : 0;
            float lv[4] = {l0, l1, l2, l3};
            int   sgv[4] = {sgv0, sgv1, sgv2, sgv3};
            #pragma unroll
            for (int j = 0; j < 4; j++) {
                int q = qb + j;
                int t = q >> 2;
                bool ok = (s <= cur + t) && (kvv == sgv[t]);
                P[q * 65 + sl] = ok ? lv[j] * SCALE_ : -3e38f;
            }
        }
        __syncthreads();

        // ---- online softmax: warp w owns queries {2w, 2w+1} ----
        #pragma unroll
        for (int j = 0; j < 2; j++) {
            int q = (w << 1) + j;
            float v0 = P[q * 65 + lane];
            float v1 = P[q * 65 + lane + 32];
            float cm = fmaxf(v0, v1);
            #pragma unroll
            for (int o = 16; o; o >>= 1) cm = fmaxf(cm, __shfl_xor_sync(0xffffffffu, cm, o));
            float mold = SM_M[q];
            float mnew = fmaxf(mold, cm);
            float e0 = (v0 < -1e37f) ? 0.f : __expf(v0 - mnew);
            float e1 = (v1 < -1e37f) ? 0.f : __expf(v1 - mnew);
            P[q * 65 + lane]      = e0;
            P[q * 65 + lane + 32] = e1;
            float sum = e0 + e1;
            #pragma unroll
            for (int o = 16; o; o >>= 1) sum += __shfl_xor_sync(0xffffffffu, sum, o);
            if (lane == 0) {
                float f = (mold < -1e37f) ? 0.f : __expf(mold - mnew);
                SM_F[q] = f;
                SM_L[q] = SM_L[q] * f + sum;
                SM_M[q] = mnew;
            }
        }
        __syncthreads();

        // ---- PV: warp w accumulates its 2 queries, lane owns 4 dims ----
        {
            float f0 = SM_F[(w << 1)];
            float f1 = SM_F[(w << 1) + 1];
            a00*=f0; a01*=f0; a02*=f0; a03*=f0;
            a10*=f1; a11*=f1; a12*=f1; a13*=f1;
            const float* p0    = P + (w << 1) * 65;
            const float* p1    = p0 + 65;
            const float* vbase = VS + (lane << 2);
            #pragma unroll 8
            for (int ssi = 0; ssi < 64; ssi++) {
                float w0 = p0[ssi], w1 = p1[ssi];
                float4 vv = *(const float4*)(vbase + ssi * 132);
                a00 = fmaf(w0, vv.x, a00); a01 = fmaf(w0, vv.y, a01);
                a02 = fmaf(w0, vv.z, a02); a03 = fmaf(w0, vv.w, a03);
                a10 = fmaf(w1, vv.x, a10); a11 = fmaf(w1, vv.y, a11);
                a12 = fmaf(w1, vv.z, a12); a13 = fmaf(w1, vv.w, a13);
            }
        }
        __syncthreads();
    }

    // ---- write partials (unnormalized) ----
    {
        int pbase = ((b * G_ + g) * NS + sp) * 16;
        int q0i = (w << 1);
        int q1i = q0i + 1;
        *(float4*)(g_pacc + (size_t)(pbase + q0i) * 128 + (lane << 2))
            = make_float4(a00, a01, a02, a03);
        *(float4*)(g_pacc + (size_t)(pbase + q1i) * 128 + (lane << 2))
            = make_float4(a10, a11, a12, a13);
        if (lane == 0) {
            g_pm[pbase + q0i] = SM_M[q0i];  g_pl[pbase + q0i] = SM_L[q0i];
            g_pm[pbase + q1i] = SM_M[q1i];  g_pl[pbase + q1i] = SM_L[q1i];
        }
    }
}

// ---------------- K3b: combine split partials ----------------
__global__ void combine_kernel() {
    int bg  = blockIdx.x;              // 0..127 = b*G+g
    int tid = threadIdx.x;             // 256
    int q   = tid >> 4;                // 0..15
    int kb  = (tid & 15) << 3;         // 8 dims
    int base = bg * NS * 16;

    float m = -3e38f;
    #pragma unroll
    for (int s = 0; s < NS; s++) m = fmaxf(m, g_pm[base + s * 16 + q]);

    float lsum = 0.f;
    float o[8];
    #pragma unroll
    for (int j = 0; j < 8; j++) o[j] = 0.f;

    #pragma unroll
    for (int s = 0; s < NS; s++) {
        float ms  = g_pm[base + s * 16 + q];
        float wgt = (ms < -1e37f) ? 0.f : __expf(ms - m);
        lsum += wgt * g_pl[base + s * 16 + q];
        const float* pa = g_pacc + (size_t)(base + s * 16 + q) * 128 + kb;
        float4 x0 = *(const float4*)pa;
        float4 x1 = *(const float4*)(pa + 4);
        o[0] = fmaf(wgt, x0.x, o[0]); o[1] = fmaf(wgt, x0.y, o[1]);
        o[2] = fmaf(wgt, x0.z, o[2]); o[3] = fmaf(wgt, x0.w, o[3]);
        o[4] = fmaf(wgt, x1.x, o[4]); o[5] = fmaf(wgt, x1.y, o[5]);
        o[6] = fmaf(wgt, x1.z, o[6]); o[7] = fmaf(wgt, x1.w, o[7]);
    }
    float inv = (lsum > 0.f) ? (1.0f / lsum) : 0.f;
    int b = bg >> 2, g = bg & 3;
    int t = q >> 2, r = q & 3;
    float* dst = g_attn + (((b * T_ + t) * H_ + g * NREP + r) << 7) + kb;
    *(float4*)dst       = make_float4(o[0]*inv, o[1]*inv, o[2]*inv, o[3]*inv);
    *(float4*)(dst + 4) = make_float4(o[4]*inv, o[5]*inv, o[6]*inv, o[7]*inv);
}

// ---------------- host launch ----------------
extern "C" void kernel_launch(void* const* d_in, const int* in_sizes, int n_in,
                              void* d_out, int out_size) {
    const float* hidden = (const float*)d_in[0];
    const int*   seg    = (const int*)  d_in[1];
    const float* kc     = (const float*)d_in[2];
    const float* vc     = (const float*)d_in[3];
    const float* Wq     = (const float*)d_in[4];
    const float* Wk     = (const float*)d_in[5];
    const float* Wv     = (const float*)d_in[6];
    const float* Wo     = (const float*)d_in[7];
    const float* qsc    = (const float*)d_in[8];
    const float* ksc    = (const float*)d_in[9];
    const int*   curp   = (const int*)  d_in[10];

    (void)in_sizes; (void)n_in; (void)out_size;

    pos_kernel<<<1, 32>>>(seg, curp);
    gemm_kernel<<<dim3(48, 4), 128>>>(hidden, Wq, Wk, Wv, nullptr, 3072, 1);
    normrope_kernel<<<dim3(24, 128), 128>>>(qsc, ksc);
    cudaFuncSetAttribute(attn_kernel, cudaFuncAttributeMaxDynamicSharedMemorySize,
                         ATTN_SMEM_BYTES);
    attn_kernel<<<dim3(B_, G_, NS), 256, ATTN_SMEM_BYTES>>>(kc, vc, seg, curp);
    combine_kernel<<<128, 256>>>();
    gemm_kernel<<<dim3(32, 4), 128>>>(nullptr, Wo, Wo, Wo, (float*)d_out, 2048, 0);
}

// round 10
// speedup vs baseline: 1.9585x; 1.2159x over previous
#include <cuda_runtime.h>
#include <cuda_bf16.h>
#include <stdint.h>
#include <stddef.h>

// Problem constants
#define B_   32
#define T_   4
#define D_   2048
#define H_   16
#define G_   4
#define K_   128
#define S_   4096
#define NREP 4
#define NS   4            // sequence splits for attention
#define SCALE_ 0.08838834764831845f   // K^-0.5
#define EPS_   1e-6f

// ---------------- device scratch (no allocations allowed) ----------------
__device__ __align__(16) float g_qkv[128 * 3072];       // raw projections
__device__ __align__(16) float g_q  [128 * H_ * K_];    // post norm+rope
__device__ __align__(16) float g_kn [128 * G_ * K_];    // new K rows
__device__ __align__(16) float g_vn [128 * G_ * K_];    // new V rows
__device__ __align__(16) float g_attn[128 * H_ * K_];   // attention out
__device__ int   g_pos[128];              // rope position per (b,t)
__device__ int   g_start[B_];             // left pads per b
// split-attention partials
__device__ __align__(16) float g_pacc[B_ * G_ * NS * 16 * 128];
__device__ float g_pm  [B_ * G_ * NS * 16];
__device__ float g_pl  [B_ * G_ * NS * 16];

// ---------------- cp.async helpers ----------------
__device__ __forceinline__ void cp_async16(uint32_t dst, const void* src, bool p) {
    // src-size operand: 16 = copy, 0 = zero-fill destination
    asm volatile("cp.async.cg.shared.global [%0], [%1], 16, %2;\n"
                 :: "r"(dst), "l"(src), "r"(p ? 16 : 0));
}
__device__ __forceinline__ void cp_commit() {
    asm volatile("cp.async.commit_group;\n" ::);
}
template<int N> __device__ __forceinline__ void cp_wait() {
    asm volatile("cp.async.wait_group %0;\n" :: "n"(N));
}

// ---------------- K0: positions / left pads ----------------
__global__ void pos_kernel(const int* __restrict__ seg, const int* __restrict__ curp) {
    int b = threadIdx.x;
    if (b >= B_) return;
    int cur = *curp;
    int c = 0, lp = 0;
    for (int t = 0; t < T_; t++) {
        int v = (seg[b * T_ + t] != 0) ? 1 : 0;
        c += v;
        if (c == 0) lp++;
        g_pos[b * T_ + t] = c - 1 + cur;
    }
    g_start[b] = lp;
}

// ---------------- GEMM: 32x64 tile, 128 thr, 4x4 reg tile ----------------
// double-buffered smem, register prefetch (unchanged from passing R9 version)
__global__ __launch_bounds__(128) void gemm_kernel(
    const float* __restrict__ A_,
    const float* __restrict__ W0, const float* __restrict__ W1,
    const float* __restrict__ W2,
    float* __restrict__ C_, int ldc, int qkv)
{
    __shared__ alignas(16) float As[2][32][33];   // [buf][k][m] padded
    __shared__ alignas(16) float Bs[2][32][68];   // [buf][k][n] padded

    const float* A = A_ ? A_ : (const float*)g_attn;
    float*       C = C_ ? C_ : (float*)g_qkv;

    int c0 = blockIdx.x * 64;
    const float* W; int ldb, cb;
    if (qkv) {
        if (c0 < 2048)      { W = W0; ldb = 2048; cb = c0; }
        else if (c0 < 2560) { W = W1; ldb = 512;  cb = c0 - 2048; }
        else                { W = W2; ldb = 512;  cb = c0 - 2560; }
    } else                  { W = W0; ldb = 2048; cb = c0; }

    int m0  = blockIdx.y * 32;
    int tid = threadIdx.x;          // 128
    int tx  = tid & 15;             // 16 cols of 4
    int ty  = tid >> 4;             // 8 rows of 4

    int am0 = tid >> 3;             // A: j=0 row
    int ak  = (tid & 7) << 2;       // A: k quad
    int br  = tid >> 4;             // B: j=0 row
    int bn  = (tid & 15) << 2;      // B: n quad

    float4 ra[2], rb[4];

    auto gload = [&](int it) {
        int k0 = it << 5;
        ra[0] = *(const float4*)(A + (size_t)(m0 + am0)      * 2048 + k0 + ak);
        ra[1] = *(const float4*)(A + (size_t)(m0 + am0 + 16) * 2048 + k0 + ak);
        #pragma unroll
        for (int j = 0; j < 4; j++)
            rb[j] = *(const float4*)(W + (size_t)(k0 + br + j * 8) * ldb + cb + bn);
    };
    auto sstore = [&](int buf) {
        #pragma unroll
        for (int j = 0; j < 2; j++) {
            int am = am0 + j * 16;
            As[buf][ak + 0][am] = ra[j].x;
            As[buf][ak + 1][am] = ra[j].y;
            As[buf][ak + 2][am] = ra[j].z;
            As[buf][ak + 3][am] = ra[j].w;
        }
        #pragma unroll
        for (int j = 0; j < 4; j++)
            *(float4*)&Bs[buf][br + j * 8][bn] = rb[j];
    };

    float acc[4][4];
    #pragma unroll
    for (int i = 0; i < 4; i++)
        #pragma unroll
        for (int j = 0; j < 4; j++) acc[i][j] = 0.f;

    gload(0);
    sstore(0);
    __syncthreads();

    for (int it = 0; it < 64; it++) {
        int bf = it & 1;
        if (it < 63) gload(it + 1);
        #pragma unroll
        for (int kk = 0; kk < 32; kk++) {
            float a0 = As[bf][kk][ty * 4 + 0];
            float a1 = As[bf][kk][ty * 4 + 1];
            float a2 = As[bf][kk][ty * 4 + 2];
            float a3 = As[bf][kk][ty * 4 + 3];
            float4 bv = *(const float4*)&Bs[bf][kk][tx << 2];
            acc[0][0] = fmaf(a0, bv.x, acc[0][0]);
            acc[0][1] = fmaf(a0, bv.y, acc[0][1]);
            acc[0][2] = fmaf(a0, bv.z, acc[0][2]);
            acc[0][3] = fmaf(a0, bv.w, acc[0][3]);
            acc[1][0] = fmaf(a1, bv.x, acc[1][0]);
            acc[1][1] = fmaf(a1, bv.y, acc[1][1]);
            acc[1][2] = fmaf(a1, bv.z, acc[1][2]);
            acc[1][3] = fmaf(a1, bv.w, acc[1][3]);
            acc[2][0] = fmaf(a2, bv.x, acc[2][0]);
            acc[2][1] = fmaf(a2, bv.y, acc[2][1]);
            acc[2][2] = fmaf(a2, bv.z, acc[2][2]);
            acc[2][3] = fmaf(a2, bv.w, acc[2][3]);
            acc[3][0] = fmaf(a3, bv.x, acc[3][0]);
            acc[3][1] = fmaf(a3, bv.y, acc[3][1]);
            acc[3][2] = fmaf(a3, bv.z, acc[3][2]);
            acc[3][3] = fmaf(a3, bv.w, acc[3][3]);
        }
        __syncthreads();
        if (it < 63) {
            sstore(bf ^ 1);
            __syncthreads();
        }
    }

    #pragma unroll
    for (int i = 0; i < 4; i++) {
        float* cp = C + (size_t)(m0 + ty * 4 + i) * ldc + c0 + (tx << 2);
        *(float4*)cp = make_float4(acc[i][0], acc[i][1], acc[i][2], acc[i][3]);
    }
}

// ---------------- K2: rmsnorm + rope + split ----------------
__global__ void normrope_kernel(const float* __restrict__ q_scale,
                                const float* __restrict__ k_scale)
{
    int slot = blockIdx.x;
    int m    = blockIdx.y;
    int tid  = threadIdx.x;

    int cbase, type, gi = 0;
    if (slot < 16)      { cbase = slot * 128;               type = 0; }
    else if (slot < 20) { cbase = 2048 + (slot - 16) * 128; type = 1; gi = slot - 16; }
    else                { cbase = 2560 + (slot - 20) * 128; type = 2; gi = slot - 20; }

    float x = g_qkv[m * 3072 + cbase + tid];

    if (type == 2) {   // V: no norm, no rope
        g_vn[(m * G_ + gi) * K_ + tid] = x;
        return;
    }

    __shared__ float wsum[4];
    __shared__ float sx[128];

    float ss = x * x;
    #pragma unroll
    for (int o = 16; o; o >>= 1) ss += __shfl_xor_sync(0xffffffffu, ss, o);
    if ((tid & 31) == 0) wsum[tid >> 5] = ss;
    __syncthreads();
    float var = (wsum[0] + wsum[1] + wsum[2] + wsum[3]) * (1.0f / 128.0f);

    float sc = (type == 0) ? q_scale[tid] : k_scale[tid];
    float xn = x * rsqrtf(var + EPS_) * sc;
    sx[tid] = xn;
    __syncthreads();

    int   pos = g_pos[m];
    int   j   = tid & 63;
    float fr  = (float)j * (1.0f / 64.0f);
    float ts  = powf(10000.0f, fr);
    float ang = (float)pos / ts;
    float sv, cv;
    sincosf(ang, &sv, &cv);

    float out = (tid < 64) ? (sx[j] * cv - sx[j + 64] * sv)
                           : (sx[j + 64] * cv + sx[j] * sv);

    if (type == 0) g_q [(m * H_ + slot) * K_ + tid] = out;
    else           g_kn[(m * G_ + gi)  * K_ + tid] = out;
}

// ---------------- K3: split flash attention, cp.async pipelined ----------------
// dyn smem floats: QS[2048] | KS[64*132] | VS[64*132] | P[16*65] | M/L/F[48]
#define ATTN_SMEM_FLOATS (2048 + 8448 + 8448 + 1040 + 48)
#define ATTN_SMEM_BYTES  (ATTN_SMEM_FLOATS * 4)

__global__ __launch_bounds__(256, 2) void attn_kernel(
    const float* __restrict__ kc,
    const float* __restrict__ vc,
    const int*   __restrict__ seg,
    const int*   __restrict__ curp)
{
    extern __shared__ float smf[];
    float* QS   = smf;
    float* KS   = smf + 2048;
    float* VS   = KS + 8448;
    float* P    = VS + 8448;
    float* SM_M = P + 1040;
    float* SM_L = SM_M + 16;
    float* SM_F = SM_L + 16;

    int b  = blockIdx.x;
    int g  = blockIdx.y;
    int sp = blockIdx.z;
    int tid  = threadIdx.x;            // 256
    int w    = tid >> 5;
    int lane = tid & 31;

    int cur   = *curp;
    int start = g_start[b];
    int s_end = cur + T_;

    int sgv0 = seg[b * T_ + 0], sgv1 = seg[b * T_ + 1];
    int sgv2 = seg[b * T_ + 2], sgv3 = seg[b * T_ + 3];

    // chunk range for this split
    int nch  = (s_end + 63) >> 6;
    int per  = (nch + NS - 1) / NS;
    int c_lo = sp * per;
    int c_hi = min(nch, c_lo + per);
    int cst  = max(c_lo, start >> 6);

    uint32_t ksb = (uint32_t)__cvta_generic_to_shared(KS);
    uint32_t vsb = (uint32_t)__cvta_generic_to_shared(VS);

    // per-thread staging coordinates (8 rows of 32 lanes-of-float4 per pass)
    auto issueK = [&](int ci) {
        int s0 = ci << 6;
        #pragma unroll
        for (int it = 0; it < 8; it++) {
            int idx = tid + (it << 8);
            int row = idx >> 5;
            int c4  = (idx & 31) << 2;
            int s   = s0 + row;
            const float* src; bool p = true;
            if (s < cur)        src = kc + ((((size_t)(b * S_ + s)) * G_ + g) << 7) + c4;
            else if (s < s_end) src = g_kn + (((b * T_ + (s - cur)) * G_ + g) << 7) + c4;
            else              { src = kc; p = false; }
            cp_async16(ksb + (uint32_t)(row * 132 + c4) * 4, src, p);
        }
    };
    auto issueV = [&](int ci) {
        int s0 = ci << 6;
        #pragma unroll
        for (int it = 0; it < 8; it++) {
            int idx = tid + (it << 8);
            int row = idx >> 5;
            int c4  = (idx & 31) << 2;
            int s   = s0 + row;
            const float* src; bool p = true;
            if (s < cur)        src = vc + ((((size_t)(b * S_ + s)) * G_ + g) << 7) + c4;
            else if (s < s_end) src = g_vn + (((b * T_ + (s - cur)) * G_ + g) << 7) + c4;
            else              { src = vc; p = false; }
            cp_async16(vsb + (uint32_t)(row * 132 + c4) * 4, src, p);
        }
    };

    // prologue: stage first chunk (K group, then V group)
    if (cst < c_hi) { issueK(cst); cp_commit(); issueV(cst); cp_commit(); }

    // load the 16 query vectors for this (b,g) (overlaps with cp.async)
    #pragma unroll
    for (int it = 0; it < 2; it++) {
        int idx = tid + (it << 8);
        int q   = idx >> 5;
        int c4  = (idx & 31) << 2;
        int t = q >> 2, r = q & 3;
        float4 qv = *(const float4*)(g_q + (((b * T_ + t) * H_ + (g * NREP + r)) << 7) + c4);
        *(float4*)(QS + q * 128 + c4) = qv;
    }
    if (tid < 16) { SM_M[tid] = -3e38f; SM_L[tid] = 0.f; }

    float a00=0,a01=0,a02=0,a03=0, a10=0,a11=0,a12=0,a13=0;
    int sl = ((w & 1) << 5) + lane;     // logits: lane's s row within chunk
    int qb = (w >> 1) << 2;             // logits: 4-query group

    __syncthreads();

    for (int ci = cst; ci < c_hi; ci++) {
        int s0 = ci << 6;
        cp_wait<1>();                   // K(ci) complete (V(ci) may be pending)
        __syncthreads();

        // ---- logits: warp computes 4 queries x its 32 s-rows ----
        {
            const float* krow = KS + sl * 132;
            const float* q0 = QS + qb * 128;
            const float* q1 = q0 + 128;
            const float* q2 = q1 + 128;
            const float* q3 = q2 + 128;
            float l0=0.f,l1=0.f,l2=0.f,l3=0.f;
            #pragma unroll
            for (int kk = 0; kk < 128; kk += 4) {
                float4 kv = *(const float4*)(krow + kk);
                float4 a;
                a = *(const float4*)(q0 + kk);
                l0 = fmaf(a.x,kv.x,l0); l0 = fmaf(a.y,kv.y,l0);
                l0 = fmaf(a.z,kv.z,l0); l0 = fmaf(a.w,kv.w,l0);
                a = *(const float4*)(q1 + kk);
                l1 = fmaf(a.x,kv.x,l1); l1 = fmaf(a.y,kv.y,l1);
                l1 = fmaf(a.z,kv.z,l1); l1 = fmaf(a.w,kv.w,l1);
                a = *(const float4*)(q2 + kk);
                l2 = fmaf(a.x,kv.x,l2); l2 = fmaf(a.y,kv.y,l2);
                l2 = fmaf(a.z,kv.z,l2); l2 = fmaf(a.w,kv.w,l2);
                a = *(const float4*)(q3 + kk);
                l3 = fmaf(a.x,kv.x,l3); l3 = fmaf(a.y,kv.y,l3);
                l3 = fmaf(a.z,kv.z,l3); l3 = fmaf(a.w,kv.w,l3);
            }
            int s   = s0 + sl;
            int kvv = (s >= start && s < s_end) ? 1 : 0;
            float lv[4] = {l0, l1, l2, l3};
            int   sgv[4] = {sgv0, sgv1, sgv2, sgv3};
            #pragma unroll
            for (int j = 0; j < 4; j++) {
                int q = qb + j;
                int t = q >> 2;
                bool ok = (s <= cur + t) && (kvv == sgv[t]);
                P[q * 65 + sl] = ok ? lv[j] * SCALE_ : -3e38f;
            }
        }
        __syncthreads();                // P written, KS fully consumed

        if (ci + 1 < c_hi) issueK(ci + 1);
        cp_commit();                    // overlaps softmax + PV

        // ---- online softmax: warp w owns queries {2w, 2w+1} ----
        #pragma unroll
        for (int j = 0; j < 2; j++) {
            int q = (w << 1) + j;
            float v0 = P[q * 65 + lane];
            float v1 = P[q * 65 + lane + 32];
            float cm = fmaxf(v0, v1);
            #pragma unroll
            for (int o = 16; o; o >>= 1) cm = fmaxf(cm, __shfl_xor_sync(0xffffffffu, cm, o));
            float mold = SM_M[q];
            float mnew = fmaxf(mold, cm);
            float e0 = (v0 < -1e37f) ? 0.f : __expf(v0 - mnew);
            float e1 = (v1 < -1e37f) ? 0.f : __expf(v1 - mnew);
            P[q * 65 + lane]      = e0;
            P[q * 65 + lane + 32] = e1;
            float sum = e0 + e1;
            #pragma unroll
            for (int o = 16; o; o >>= 1) sum += __shfl_xor_sync(0xffffffffu, sum, o);
            if (lane == 0) {
                float f = (mold < -1e37f) ? 0.f : __expf(mold - mnew);
                SM_F[q] = f;
                SM_L[q] = SM_L[q] * f + sum;
                SM_M[q] = mnew;
            }
        }
        cp_wait<1>();                   // V(ci) complete (K(ci+1) pending)
        __syncthreads();                // exp P + SM_F visible, VS ready

        // ---- PV: warp w accumulates its 2 queries, lane owns 4 dims ----
        {
            float f0 = SM_F[(w << 1)];
            float f1 = SM_F[(w << 1) + 1];
            a00*=f0; a01*=f0; a02*=f0; a03*=f0;
            a10*=f1; a11*=f1; a12*=f1; a13*=f1;
            const float* p0    = P + (w << 1) * 65;
            const float* p1    = p0 + 65;
            const float* vbase = VS + (lane << 2);
            #pragma unroll 8
            for (int ssi = 0; ssi < 64; ssi++) {
                float w0 = p0[ssi], w1 = p1[ssi];
                float4 vv = *(const float4*)(vbase + ssi * 132);
                a00 = fmaf(w0, vv.x, a00); a01 = fmaf(w0, vv.y, a01);
                a02 = fmaf(w0, vv.z, a02); a03 = fmaf(w0, vv.w, a03);
                a10 = fmaf(w1, vv.x, a10); a11 = fmaf(w1, vv.y, a11);
                a12 = fmaf(w1, vv.z, a12); a13 = fmaf(w1, vv.w, a13);
            }
        }
        __syncthreads();                // VS fully consumed

        if (ci + 1 < c_hi) issueV(ci + 1);
        cp_commit();                    // overlaps next logits
    }

    // ---- write partials (unnormalized) ----
    {
        int pbase = ((b * G_ + g) * NS + sp) * 16;
        int q0i = (w << 1);
        int q1i = q0i + 1;
        *(float4*)(g_pacc + (size_t)(pbase + q0i) * 128 + (lane << 2))
            = make_float4(a00, a01, a02, a03);
        *(float4*)(g_pacc + (size_t)(pbase + q1i) * 128 + (lane << 2))
            = make_float4(a10, a11, a12, a13);
        if (lane == 0) {
            g_pm[pbase + q0i] = SM_M[q0i];  g_pl[pbase + q0i] = SM_L[q0i];
            g_pm[pbase + q1i] = SM_M[q1i];  g_pl[pbase + q1i] = SM_L[q1i];
        }
    }
}

// ---------------- K3b: combine split partials ----------------
__global__ void combine_kernel() {
    int bg  = blockIdx.x;              // 0..127 = b*G+g
    int tid = threadIdx.x;             // 256
    int q   = tid >> 4;                // 0..15
    int kb  = (tid & 15) << 3;         // 8 dims
    int base = bg * NS * 16;

    float m = -3e38f;
    #pragma unroll
    for (int s = 0; s < NS; s++) m = fmaxf(m, g_pm[base + s * 16 + q]);

    float lsum = 0.f;
    float o[8];
    #pragma unroll
    for (int j = 0; j < 8; j++) o[j] = 0.f;

    #pragma unroll
    for (int s = 0; s < NS; s++) {
        float ms  = g_pm[base + s * 16 + q];
        float wgt = (ms < -1e37f) ? 0.f : __expf(ms - m);
        lsum += wgt * g_pl[base + s * 16 + q];
        const float* pa = g_pacc + (size_t)(base + s * 16 + q) * 128 + kb;
        float4 x0 = *(const float4*)pa;
        float4 x1 = *(const float4*)(pa + 4);
        o[0] = fmaf(wgt, x0.x, o[0]); o[1] = fmaf(wgt, x0.y, o[1]);
        o[2] = fmaf(wgt, x0.z, o[2]); o[3] = fmaf(wgt, x0.w, o[3]);
        o[4] = fmaf(wgt, x1.x, o[4]); o[5] = fmaf(wgt, x1.y, o[5]);
        o[6] = fmaf(wgt, x1.z, o[6]); o[7] = fmaf(wgt, x1.w, o[7]);
    }
    float inv = (lsum > 0.f) ? (1.0f / lsum) : 0.f;
    int b = bg >> 2, g = bg & 3;
    int t = q >> 2, r = q & 3;
    float* dst = g_attn + (((b * T_ + t) * H_ + g * NREP + r) << 7) + kb;
    *(float4*)dst       = make_float4(o[0]*inv, o[1]*inv, o[2]*inv, o[3]*inv);
    *(float4*)(dst + 4) = make_float4(o[4]*inv, o[5]*inv, o[6]*inv, o[7]*inv);
}

// ---------------- host launch ----------------
extern "C" void kernel_launch(void* const* d_in, const int* in_sizes, int n_in,
                              void* d_out, int out_size) {
    const float* hidden = (const float*)d_in[0];
    const int*   seg    = (const int*)  d_in[1];
    const float* kc     = (const float*)d_in[2];
    const float* vc     = (const float*)d_in[3];
    const float* Wq     = (const float*)d_in[4];
    const float* Wk     = (const float*)d_in[5];
    const float* Wv     = (const float*)d_in[6];
    const float* Wo     = (const float*)d_in[7];
    const float* qsc    = (const float*)d_in[8];
    const float* ksc    = (const float*)d_in[9];
    const int*   curp   = (const int*)  d_in[10];

    (void)in_sizes; (void)n_in; (void)out_size;

    pos_kernel<<<1, 32>>>(seg, curp);
    gemm_kernel<<<dim3(48, 4), 128>>>(hidden, Wq, Wk, Wv, nullptr, 3072, 1);
    normrope_kernel<<<dim3(24, 128), 128>>>(qsc, ksc);
    cudaFuncSetAttribute(attn_kernel, cudaFuncAttributeMaxDynamicSharedMemorySize,
                         ATTN_SMEM_BYTES);
    attn_kernel<<<dim3(B_, G_, NS), 256, ATTN_SMEM_BYTES>>>(kc, vc, seg, curp);
    combine_kernel<<<128, 256>>>();
    gemm_kernel<<<dim3(32, 4), 128>>>(nullptr, Wo, Wo, Wo, (float*)d_out, 2048, 0);
}

// round 11
// speedup vs baseline: 2.0672x; 1.0555x over previous
#include <cuda_runtime.h>
#include <cuda_bf16.h>
#include <stdint.h>
#include <stddef.h>

// Problem constants
#define B_   32
#define T_   4
#define D_   2048
#define H_   16
#define G_   4
#define K_   128
#define S_   4096
#define NREP 4
#define NS   4            // sequence splits for attention
#define SCALE_ 0.08838834764831845f   // K^-0.5
#define EPS_   1e-6f

// ---------------- device scratch (no allocations allowed) ----------------
__device__ __align__(16) float g_qkv[128 * 3072];       // raw projections
__device__ __align__(16) float g_q  [128 * H_ * K_];    // post norm+rope
__device__ __align__(16) float g_kn [128 * G_ * K_];    // new K rows
__device__ __align__(16) float g_vn [128 * G_ * K_];    // new V rows
__device__ __align__(16) float g_attn[128 * H_ * K_];   // attention out
// split-attention partials
__device__ __align__(16) float g_pacc[B_ * G_ * NS * 16 * 128];
__device__ float g_pm  [B_ * G_ * NS * 16];
__device__ float g_pl  [B_ * G_ * NS * 16];

// ---------------- cp.async helpers ----------------
__device__ __forceinline__ void cp_async16(uint32_t dst, const void* src, bool p) {
    asm volatile("cp.async.cg.shared.global [%0], [%1], 16, %2;\n"
                 :: "r"(dst), "l"(src), "r"(p ? 16 : 0));
}
__device__ __forceinline__ void cp_commit() {
    asm volatile("cp.async.commit_group;\n" ::);
}
template<int N> __device__ __forceinline__ void cp_wait() {
    asm volatile("cp.async.wait_group %0;\n" :: "n"(N));
}

// ---------------- GEMM: MT x 64 tile, 128 thr, (MT/8)x4 reg tile ----------------
// double-buffered smem, register prefetch; A smem [k][m] with 16B-aligned pad
// qkv=1: C_==nullptr -> C = g_qkv (ldc=3072), A = hidden, cols select Wq/Wk/Wv
// qkv=0: C = Cout (ldc=2048), A_==nullptr -> A = g_attn, W0 = Wo
template<int MT>
__global__ __launch_bounds__(128) void gemm_kernel(
    const float* __restrict__ A_,
    const float* __restrict__ W0, const float* __restrict__ W1,
    const float* __restrict__ W2,
    float* __restrict__ C_, int ldc, int qkv)
{
    constexpr int APAD = (MT == 16) ? 20 : 36;   // row pad: 20*4=80B (8B align), 36*4=144B (16B align)
    constexpr int RM   = MT / 8;                 // rows per thread: 2 or 4
    constexpr int NRA  = MT / 16;                // A float4 loads per thread: 1 or 2

    __shared__ alignas(16) float As[2][32][APAD];  // [buf][k][m]
    __shared__ alignas(16) float Bs[2][32][68];    // [buf][k][n]

    const float* A = A_ ? A_ : (const float*)g_attn;
    float*       C = C_ ? C_ : (float*)g_qkv;

    int c0 = blockIdx.x * 64;
    const float* W; int ldb, cb;
    if (qkv) {
        if (c0 < 2048)      { W = W0; ldb = 2048; cb = c0; }
        else if (c0 < 2560) { W = W1; ldb = 512;  cb = c0 - 2048; }
        else                { W = W2; ldb = 512;  cb = c0 - 2560; }
    } else                  { W = W0; ldb = 2048; cb = c0; }

    int m0  = blockIdx.y * MT;
    int tid = threadIdx.x;          // 128
    int tx  = tid & 15;             // 16 cols of 4
    int ty  = tid >> 4;             // 8 row-groups of RM

    int r   = tid >> 3;             // A row 0..15
    int kq  = (tid & 7) << 2;       // A k quad
    int br  = tid >> 4;             // B row 0..7
    int bn  = (tid & 15) << 2;      // B n quad

    float4 ra[NRA], rb[4];

    auto gload = [&](int it) {
        int k0 = it << 5;
        #pragma unroll
        for (int i = 0; i < NRA; i++)
            ra[i] = *(const float4*)(A + (size_t)(m0 + r + 16 * i) * 2048 + k0 + kq);
        #pragma unroll
        for (int j = 0; j < 4; j++)
            rb[j] = *(const float4*)(W + (size_t)(k0 + br + j * 8) * ldb + cb + bn);
    };
    auto sstore = [&](int buf) {
        #pragma unroll
        for (int i = 0; i < NRA; i++) {
            int m = r + 16 * i;
            As[buf][kq + 0][m] = ra[i].x;
            As[buf][kq + 1][m] = ra[i].y;
            As[buf][kq + 2][m] = ra[i].z;
            As[buf][kq + 3][m] = ra[i].w;
        }
        #pragma unroll
        for (int j = 0; j < 4; j++)
            *(float4*)&Bs[buf][br + j * 8][bn] = rb[j];
    };

    float acc[RM][4];
    #pragma unroll
    for (int i = 0; i < RM; i++)
        #pragma unroll
        for (int j = 0; j < 4; j++) acc[i][j] = 0.f;

    gload(0);
    sstore(0);
    __syncthreads();

    for (int it = 0; it < 64; it++) {
        int bf = it & 1;
        if (it < 63) gload(it + 1);
        #pragma unroll
        for (int kk = 0; kk < 32; kk++) {
            float av[RM];
            if (MT == 32) {
                float4 t = *(const float4*)&As[bf][kk][ty * 4];
                av[0] = t.x; av[1] = t.y;
                av[RM - 2] = t.z; av[RM - 1] = t.w;   // RM==4 here
            } else {
                float2 t = *(const float2*)&As[bf][kk][ty * 2];
                av[0] = t.x; av[1] = t.y;
            }
            float4 bv = *(const float4*)&Bs[bf][kk][tx << 2];
            #pragma unroll
            for (int i = 0; i < RM; i++) {
                acc[i][0] = fmaf(av[i], bv.x, acc[i][0]);
                acc[i][1] = fmaf(av[i], bv.y, acc[i][1]);
                acc[i][2] = fmaf(av[i], bv.z, acc[i][2]);
                acc[i][3] = fmaf(av[i], bv.w, acc[i][3]);
            }
        }
        __syncthreads();
        if (it < 63) {
            sstore(bf ^ 1);
            __syncthreads();
        }
    }

    #pragma unroll
    for (int i = 0; i < RM; i++) {
        float* cp = C + (size_t)(m0 + ty * RM + i) * ldc + c0 + (tx << 2);
        *(float4*)cp = make_float4(acc[i][0], acc[i][1], acc[i][2], acc[i][3]);
    }
}

// ---------------- K2: rmsnorm + rope + split (positions computed inline) ----------------
__global__ void normrope_kernel(const float* __restrict__ q_scale,
                                const float* __restrict__ k_scale,
                                const int*   __restrict__ seg,
                                const int*   __restrict__ curp)
{
    int slot = blockIdx.x;
    int m    = blockIdx.y;
    int tid  = threadIdx.x;

    int cbase, type, gi = 0;
    if (slot < 16)      { cbase = slot * 128;               type = 0; }
    else if (slot < 20) { cbase = 2048 + (slot - 16) * 128; type = 1; gi = slot - 16; }
    else                { cbase = 2560 + (slot - 20) * 128; type = 2; gi = slot - 20; }

    float x = g_qkv[m * 3072 + cbase + tid];

    if (type == 2) {   // V: no norm, no rope
        g_vn[(m * G_ + gi) * K_ + tid] = x;
        return;
    }

    __shared__ float wsum[4];
    __shared__ float sx[128];

    float ss = x * x;
    #pragma unroll
    for (int o = 16; o; o >>= 1) ss += __shfl_xor_sync(0xffffffffu, ss, o);
    if ((tid & 31) == 0) wsum[tid >> 5] = ss;
    __syncthreads();
    float var = (wsum[0] + wsum[1] + wsum[2] + wsum[3]) * (1.0f / 128.0f);

    float sc = (type == 0) ? q_scale[tid] : k_scale[tid];
    float xn = x * rsqrtf(var + EPS_) * sc;
    sx[tid] = xn;
    __syncthreads();

    // inline position: pos = cumsum(valid up to this t) - 1 + cur
    int bb = m >> 2, tt = m & 3;
    int csum = 0;
    #pragma unroll
    for (int t = 0; t < T_; t++)
        if (t <= tt) csum += (seg[bb * T_ + t] != 0) ? 1 : 0;
    int pos = csum - 1 + *curp;

    int   j   = tid & 63;
    float fr  = (float)j * (1.0f / 64.0f);
    float ts  = powf(10000.0f, fr);        // accurate pow (large angles)
    float ang = (float)pos / ts;
    float sv, cv;
    sincosf(ang, &sv, &cv);

    float out = (tid < 64) ? (sx[j] * cv - sx[j + 64] * sv)
                           : (sx[j + 64] * cv + sx[j] * sv);

    if (type == 0) g_q [(m * H_ + slot) * K_ + tid] = out;
    else           g_kn[(m * G_ + gi)  * K_ + tid] = out;
}

// ---------------- K3: split flash attention, cp.async pipelined ----------------
// dyn smem floats: QS[2048] | KS[64*132] | VS[64*132] | P[16*65] | M/L/F[48]
#define ATTN_SMEM_FLOATS (2048 + 8448 + 8448 + 1040 + 48)
#define ATTN_SMEM_BYTES  (ATTN_SMEM_FLOATS * 4)

__global__ __launch_bounds__(256, 2) void attn_kernel(
    const float* __restrict__ kc,
    const float* __restrict__ vc,
    const int*   __restrict__ seg,
    const int*   __restrict__ curp)
{
    extern __shared__ float smf[];
    float* QS   = smf;
    float* KS   = smf + 2048;
    float* VS   = KS + 8448;
    float* P    = VS + 8448;
    float* SM_M = P + 1040;
    float* SM_L = SM_M + 16;
    float* SM_F = SM_L + 16;

    int b  = blockIdx.x;
    int g  = blockIdx.y;
    int sp = blockIdx.z;
    int tid  = threadIdx.x;            // 256
    int w    = tid >> 5;
    int lane = tid & 31;

    int cur   = *curp;
    int s_end = cur + T_;

    int sgv0 = seg[b * T_ + 0], sgv1 = seg[b * T_ + 1];
    int sgv2 = seg[b * T_ + 2], sgv3 = seg[b * T_ + 3];

    // inline left-pads
    int start;
    {
        int csum = 0, lp = 0;
        int vv0 = (sgv0 != 0), vv1 = (sgv1 != 0), vv2 = (sgv2 != 0), vv3 = (sgv3 != 0);
        csum += vv0; if (csum == 0) lp++;
        csum += vv1; if (csum == 0) lp++;
        csum += vv2; if (csum == 0) lp++;
        csum += vv3; if (csum == 0) lp++;
        start = lp;
    }

    // chunk range for this split
    int nch  = (s_end + 63) >> 6;
    int per  = (nch + NS - 1) / NS;
    int c_lo = sp * per;
    int c_hi = min(nch, c_lo + per);
    int cst  = max(c_lo, start >> 6);

    uint32_t ksb = (uint32_t)__cvta_generic_to_shared(KS);
    uint32_t vsb = (uint32_t)__cvta_generic_to_shared(VS);

    auto issueK = [&](int ci) {
        int s0c = ci << 6;
        #pragma unroll
        for (int it = 0; it < 8; it++) {
            int idx = tid + (it << 8);
            int row = idx >> 5;
            int c4  = (idx & 31) << 2;
            int s   = s0c + row;
            const float* src; bool p = true;
            if (s < cur)        src = kc + ((((size_t)(b * S_ + s)) * G_ + g) << 7) + c4;
            else if (s < s_end) src = g_kn + (((b * T_ + (s - cur)) * G_ + g) << 7) + c4;
            else              { src = kc; p = false; }
            cp_async16(ksb + (uint32_t)(row * 132 + c4) * 4, src, p);
        }
    };
    auto issueV = [&](int ci) {
        int s0c = ci << 6;
        #pragma unroll
        for (int it = 0; it < 8; it++) {
            int idx = tid + (it << 8);
            int row = idx >> 5;
            int c4  = (idx & 31) << 2;
            int s   = s0c + row;
            const float* src; bool p = true;
            if (s < cur)        src = vc + ((((size_t)(b * S_ + s)) * G_ + g) << 7) + c4;
            else if (s < s_end) src = g_vn + (((b * T_ + (s - cur)) * G_ + g) << 7) + c4;
            else              { src = vc; p = false; }
            cp_async16(vsb + (uint32_t)(row * 132 + c4) * 4, src, p);
        }
    };

    // prologue: stage first chunk (K group, then V group)
    if (cst < c_hi) { issueK(cst); cp_commit(); issueV(cst); cp_commit(); }

    // load the 16 query vectors for this (b,g) (overlaps with cp.async)
    #pragma unroll
    for (int it = 0; it < 2; it++) {
        int idx = tid + (it << 8);
        int q   = idx >> 5;
        int c4  = (idx & 31) << 2;
        int t = q >> 2, rr = q & 3;
        float4 qv = *(const float4*)(g_q + (((b * T_ + t) * H_ + (g * NREP + rr)) << 7) + c4);
        *(float4*)(QS + q * 128 + c4) = qv;
    }
    if (tid < 16) { SM_M[tid] = -3e38f; SM_L[tid] = 0.f; }

    // PV mapping: warp -> 4-query group x 32-row half
    int qg = w >> 1;                    // query group 0..3 (queries 4qg..4qg+3)
    int sh = w & 1;                     // s-half 0/1 (rows 32sh..32sh+31)
    float acc0[4] = {0,0,0,0}, acc1[4] = {0,0,0,0};
    float acc2[4] = {0,0,0,0}, acc3[4] = {0,0,0,0};

    int sl = ((w & 1) << 5) + lane;     // logits: lane's s row within chunk
    int qb = (w >> 1) << 2;             // logits: 4-query group

    __syncthreads();

    for (int ci = cst; ci < c_hi; ci++) {
        int s0 = ci << 6;
        cp_wait<1>();                   // K(ci) complete (V(ci) may be pending)
        __syncthreads();

        // ---- logits: warp computes 4 queries x its 32 s-rows ----
        {
            const float* krow = KS + sl * 132;
            const float* q0 = QS + qb * 128;
            const float* q1 = q0 + 128;
            const float* q2 = q1 + 128;
            const float* q3 = q2 + 128;
            float l0=0.f,l1=0.f,l2=0.f,l3=0.f;
            #pragma unroll
            for (int kk = 0; kk < 128; kk += 4) {
                float4 kv = *(const float4*)(krow + kk);
                float4 a;
                a = *(const float4*)(q0 + kk);
                l0 = fmaf(a.x,kv.x,l0); l0 = fmaf(a.y,kv.y,l0);
                l0 = fmaf(a.z,kv.z,l0); l0 = fmaf(a.w,kv.w,l0);
                a = *(const float4*)(q1 + kk);
                l1 = fmaf(a.x,kv.x,l1); l1 = fmaf(a.y,kv.y,l1);
                l1 = fmaf(a.z,kv.z,l1); l1 = fmaf(a.w,kv.w,l1);
                a = *(const float4*)(q2 + kk);
                l2 = fmaf(a.x,kv.x,l2); l2 = fmaf(a.y,kv.y,l2);
                l2 = fmaf(a.z,kv.z,l2); l2 = fmaf(a.w,kv.w,l2);
                a = *(const float4*)(q3 + kk);
                l3 = fmaf(a.x,kv.x,l3); l3 = fmaf(a.y,kv.y,l3);
                l3 = fmaf(a.z,kv.z,l3); l3 = fmaf(a.w,kv.w,l3);
            }
            int s   = s0 + sl;
            int kvv = (s >= start && s < s_end) ? 1 : 0;
            float lv[4] = {l0, l1, l2, l3};
            int   sgv[4] = {sgv0, sgv1, sgv2, sgv3};
            #pragma unroll
            for (int j = 0; j < 4; j++) {
                int q = qb + j;
                int t = q >> 2;
                bool ok = (s <= cur + t) && (kvv == sgv[t]);
                P[q * 65 + sl] = ok ? lv[j] * SCALE_ : -3e38f;
            }
        }
        __syncthreads();                // P written, KS fully consumed

        if (ci + 1 < c_hi) issueK(ci + 1);
        cp_commit();                    // overlaps softmax + PV

        // ---- online softmax: warp w owns queries {2w, 2w+1} ----
        #pragma unroll
        for (int j = 0; j < 2; j++) {
            int q = (w << 1) + j;
            float v0 = P[q * 65 + lane];
            float v1 = P[q * 65 + lane + 32];
            float cm = fmaxf(v0, v1);
            #pragma unroll
            for (int o = 16; o; o >>= 1) cm = fmaxf(cm, __shfl_xor_sync(0xffffffffu, cm, o));
            float mold = SM_M[q];
            float mnew = fmaxf(mold, cm);
            float e0 = (v0 < -1e37f) ? 0.f : __expf(v0 - mnew);
            float e1 = (v1 < -1e37f) ? 0.f : __expf(v1 - mnew);
            P[q * 65 + lane]      = e0;
            P[q * 65 + lane + 32] = e1;
            float sum = e0 + e1;
            #pragma unroll
            for (int o = 16; o; o >>= 1) sum += __shfl_xor_sync(0xffffffffu, sum, o);
            if (lane == 0) {
                float f = (mold < -1e37f) ? 0.f : __expf(mold - mnew);
                SM_F[q] = f;
                SM_L[q] = SM_L[q] * f + sum;
                SM_M[q] = mnew;
            }
        }
        cp_wait<1>();                   // V(ci) complete (K(ci+1) pending)
        __syncthreads();                // exp P + SM_F visible, VS ready

        // ---- PV: warp = 4 queries x its 32-row half, lane owns 4 dims ----
        {
            int qb4 = qg << 2;
            float f0 = SM_F[qb4 + 0], f1 = SM_F[qb4 + 1];
            float f2 = SM_F[qb4 + 2], f3 = SM_F[qb4 + 3];
            #pragma unroll
            for (int d = 0; d < 4; d++) {
                acc0[d] *= f0; acc1[d] *= f1; acc2[d] *= f2; acc3[d] *= f3;
            }
            const float* p0 = P + (qb4 + 0) * 65 + (sh << 5);
            const float* p1 = P + (qb4 + 1) * 65 + (sh << 5);
            const float* p2 = P + (qb4 + 2) * 65 + (sh << 5);
            const float* p3 = P + (qb4 + 3) * 65 + (sh << 5);
            const float* vbase = VS + (sh << 5) * 132 + (lane << 2);
            #pragma unroll 8
            for (int ssi = 0; ssi < 32; ssi++) {
                float4 vv = *(const float4*)(vbase + ssi * 132);
                float w0 = p0[ssi], w1 = p1[ssi], w2 = p2[ssi], w3 = p3[ssi];
                acc0[0]=fmaf(w0,vv.x,acc0[0]); acc0[1]=fmaf(w0,vv.y,acc0[1]);
                acc0[2]=fmaf(w0,vv.z,acc0[2]); acc0[3]=fmaf(w0,vv.w,acc0[3]);
                acc1[0]=fmaf(w1,vv.x,acc1[0]); acc1[1]=fmaf(w1,vv.y,acc1[1]);
                acc1[2]=fmaf(w1,vv.z,acc1[2]); acc1[3]=fmaf(w1,vv.w,acc1[3]);
                acc2[0]=fmaf(w2,vv.x,acc2[0]); acc2[1]=fmaf(w2,vv.y,acc2[1]);
                acc2[2]=fmaf(w2,vv.z,acc2[2]); acc2[3]=fmaf(w2,vv.w,acc2[3]);
                acc3[0]=fmaf(w3,vv.x,acc3[0]); acc3[1]=fmaf(w3,vv.y,acc3[1]);
                acc3[2]=fmaf(w3,vv.z,acc3[2]); acc3[3]=fmaf(w3,vv.w,acc3[3]);
            }
        }
        __syncthreads();                // VS fully consumed

        if (ci + 1 < c_hi) issueV(ci + 1);
        cp_commit();                    // overlaps next logits
    }

    // ---- merge s-halves and write partials (unnormalized) ----
    // sh==1 warps stash partials in KS (free now), sh==0 warps add + write gmem
    {
        int qb4 = qg << 2;
        if (sh == 1) {
            *(float4*)(KS + (qb4+0)*128 + (lane<<2)) = make_float4(acc0[0],acc0[1],acc0[2],acc0[3]);
            *(float4*)(KS + (qb4+1)*128 + (lane<<2)) = make_float4(acc1[0],acc1[1],acc1[2],acc1[3]);
            *(float4*)(KS + (qb4+2)*128 + (lane<<2)) = make_float4(acc2[0],acc2[1],acc2[2],acc2[3]);
            *(float4*)(KS + (qb4+3)*128 + (lane<<2)) = make_float4(acc3[0],acc3[1],acc3[2],acc3[3]);
        }
        __syncthreads();
        if (sh == 0) {
            int pbase = ((b * G_ + g) * NS + sp) * 16;
            float* accs[4] = {acc0, acc1, acc2, acc3};
            #pragma unroll
            for (int j = 0; j < 4; j++) {
                int q = qb4 + j;
                float4 pj = *(const float4*)(KS + q*128 + (lane<<2));
                *(float4*)(g_pacc + (size_t)(pbase + q) * 128 + (lane << 2))
                    = make_float4(accs[j][0]+pj.x, accs[j][1]+pj.y,
                                  accs[j][2]+pj.z, accs[j][3]+pj.w);
                if (lane == 0) {
                    g_pm[pbase + q] = SM_M[q];
                    g_pl[pbase + q] = SM_L[q];
                }
            }
        }
    }
}

// ---------------- K3b: combine split partials ----------------
__global__ void combine_kernel() {
    int bg  = blockIdx.x;              // 0..127 = b*G+g
    int tid = threadIdx.x;             // 256
    int q   = tid >> 4;                // 0..15
    int kb  = (tid & 15) << 3;         // 8 dims
    int base = bg * NS * 16;

    float m = -3e38f;
    #pragma unroll
    for (int s = 0; s < NS; s++) m = fmaxf(m, g_pm[base + s * 16 + q]);

    float lsum = 0.f;
    float o[8];
    #pragma unroll
    for (int j = 0; j < 8; j++) o[j] = 0.f;

    #pragma unroll
    for (int s = 0; s < NS; s++) {
        float ms  = g_pm[base + s * 16 + q];
        float wgt = (ms < -1e37f) ? 0.f : __expf(ms - m);
        lsum += wgt * g_pl[base + s * 16 + q];
        const float* pa = g_pacc + (size_t)(base + s * 16 + q) * 128 + kb;
        float4 x0 = *(const float4*)pa;
        float4 x1 = *(const float4*)(pa + 4);
        o[0] = fmaf(wgt, x0.x, o[0]); o[1] = fmaf(wgt, x0.y, o[1]);
        o[2] = fmaf(wgt, x0.z, o[2]); o[3] = fmaf(wgt, x0.w, o[3]);
        o[4] = fmaf(wgt, x1.x, o[4]); o[5] = fmaf(wgt, x1.y, o[5]);
        o[6] = fmaf(wgt, x1.z, o[6]); o[7] = fmaf(wgt, x1.w, o[7]);
    }
    float inv = (lsum > 0.f) ? (1.0f / lsum) : 0.f;
    int b = bg >> 2, g = bg & 3;
    int t = q >> 2, r = q & 3;
    float* dst = g_attn + (((b * T_ + t) * H_ + g * NREP + r) << 7) + kb;
    *(float4*)dst       = make_float4(o[0]*inv, o[1]*inv, o[2]*inv, o[3]*inv);
    *(float4*)(dst + 4) = make_float4(o[4]*inv, o[5]*inv, o[6]*inv, o[7]*inv);
}

// ---------------- host launch ----------------
extern "C" void kernel_launch(void* const* d_in, const int* in_sizes, int n_in,
                              void* d_out, int out_size) {
    const float* hidden = (const float*)d_in[0];
    const int*   seg    = (const int*)  d_in[1];
    const float* kc     = (const float*)d_in[2];
    const float* vc     = (const float*)d_in[3];
    const float* Wq     = (const float*)d_in[4];
    const float* Wk     = (const float*)d_in[5];
    const float* Wv     = (const float*)d_in[6];
    const float* Wo     = (const float*)d_in[7];
    const float* qsc    = (const float*)d_in[8];
    const float* ksc    = (const float*)d_in[9];
    const int*   curp   = (const int*)  d_in[10];

    (void)in_sizes; (void)n_in; (void)out_size;

    gemm_kernel<16><<<dim3(48, 8), 128>>>(hidden, Wq, Wk, Wv, nullptr, 3072, 1);
    normrope_kernel<<<dim3(24, 128), 128>>>(qsc, ksc, seg, curp);
    cudaFuncSetAttribute(attn_kernel, cudaFuncAttributeMaxDynamicSharedMemorySize,
                         ATTN_SMEM_BYTES);
    attn_kernel<<<dim3(B_, G_, NS), 256, ATTN_SMEM_BYTES>>>(kc, vc, seg, curp);
    combine_kernel<<<128, 256>>>();
    gemm_kernel<32><<<dim3(32, 4), 128>>>(nullptr, Wo, Wo, Wo, (float*)d_out, 2048, 0);
}

// round 12
// speedup vs baseline: 2.1451x; 1.0377x over previous
#include <cuda_runtime.h>
#include <cuda_bf16.h>
#include <stdint.h>
#include <stddef.h>

// Problem constants
#define B_   32
#define T_   4
#define D_   2048
#define H_   16
#define G_   4
#define K_   128
#define S_   4096
#define NREP 4
#define NS   4            // sequence splits for attention
#define SCALE_ 0.08838834764831845f   // K^-0.5
#define EPS_   1e-6f

// ---------------- device scratch (no allocations allowed) ----------------
__device__ __align__(16) float g_qkv[128 * 3072];       // raw projections
__device__ __align__(16) float g_q  [128 * H_ * K_];    // post norm+rope
__device__ __align__(16) float g_kn [128 * G_ * K_];    // new K rows
__device__ __align__(16) float g_vn [128 * G_ * K_];    // new V rows
__device__ __align__(16) float g_attn[128 * H_ * K_];   // attention out
// split-attention partials
__device__ __align__(16) float g_pacc[B_ * G_ * NS * 16 * 128];
__device__ float g_pm  [B_ * G_ * NS * 16];
__device__ float g_pl  [B_ * G_ * NS * 16];

// ---------------- cp.async helpers ----------------
__device__ __forceinline__ void cp_async16(uint32_t dst, const void* src, bool p) {
    asm volatile("cp.async.cg.shared.global [%0], [%1], 16, %2;\n"
                 :: "r"(dst), "l"(src), "r"(p ? 16 : 0));
}
__device__ __forceinline__ void cp_commit() {
    asm volatile("cp.async.commit_group;\n" ::);
}
template<int N> __device__ __forceinline__ void cp_wait() {
    asm volatile("cp.async.wait_group %0;\n" :: "n"(N));
}

// ---------------- tf32 mma helpers ----------------
__device__ __forceinline__ uint32_t cvt_tf32(float x) {
    uint32_t u;
    asm("cvt.rna.tf32.f32 %0, %1;" : "=r"(u) : "f"(x));
    return u;
}
__device__ __forceinline__ void mma_tf32(float c[4],
    uint32_t a0, uint32_t a1, uint32_t a2, uint32_t a3,
    uint32_t b0, uint32_t b1)
{
    asm volatile(
        "mma.sync.aligned.m16n8k8.row.col.f32.tf32.tf32.f32 "
        "{%0,%1,%2,%3}, {%4,%5,%6,%7}, {%8,%9}, {%0,%1,%2,%3};\n"
        : "+f"(c[0]), "+f"(c[1]), "+f"(c[2]), "+f"(c[3])
        : "r"(a0), "r"(a1), "r"(a2), "r"(a3), "r"(b0), "r"(b1));
}

// ---------------- GEMM: tf32 mma, 64x64 tile, 128 thr, cp.async 2-stage ------
// qkv=1: C_==nullptr -> C = g_qkv (ldc=3072), A = hidden, cols select Wq/Wk/Wv
// qkv=0: C = Cout (ldc=2048), A_==nullptr -> A = g_attn, W0 = Wo
__global__ __launch_bounds__(128) void mma_gemm_kernel(
    const float* __restrict__ A_,
    const float* __restrict__ W0, const float* __restrict__ W1,
    const float* __restrict__ W2,
    float* __restrict__ C_, int ldc, int qkv)
{
    __shared__ alignas(16) float As[2][64][20];   // [buf][m][k], row stride 20
    __shared__ alignas(16) float Ws[2][16][72];   // [buf][k][n], row stride 72

    const float* A = A_ ? A_ : (const float*)g_attn;
    float*       C = C_ ? C_ : (float*)g_qkv;

    int c0 = blockIdx.x * 64;
    const float* W; int ldb, cb;
    if (qkv) {
        if (c0 < 2048)      { W = W0; ldb = 2048; cb = c0; }
        else if (c0 < 2560) { W = W1; ldb = 512;  cb = c0 - 2048; }
        else                { W = W2; ldb = 512;  cb = c0 - 2560; }
    } else                  { W = W0; ldb = 2048; cb = c0; }

    int m0   = blockIdx.y * 64;
    int tid  = threadIdx.x;           // 128
    int wid  = tid >> 5;
    int lane = tid & 31;
    int gq   = lane >> 2;             // group id 0..7
    int tg   = lane & 3;              // thread-in-group 0..3
    int wm0  = (wid >> 1) << 5;       // warp m offset 0/32
    int wn0  = (wid & 1) << 5;        // warp n offset 0/32

    uint32_t sAs = (uint32_t)__cvta_generic_to_shared(&As[0][0][0]);
    uint32_t sWs = (uint32_t)__cvta_generic_to_shared(&Ws[0][0][0]);

    auto issue = [&](int it, int buf) {
        int k0 = it << 4;
        #pragma unroll
        for (int j = 0; j < 2; j++) {                // A: 64 rows x 16 cols
            int idx = tid + (j << 7);                // 0..255 float4
            int row = idx >> 2, q = (idx & 3) << 2;
            cp_async16(sAs + (uint32_t)(buf * 1280 + row * 20 + q) * 4,
                       A + (size_t)(m0 + row) * 2048 + k0 + q, true);
        }
        #pragma unroll
        for (int j = 0; j < 2; j++) {                // W: 16 rows x 64 cols
            int idx = tid + (j << 7);                // 0..255 float4
            int row = idx >> 4, q = (idx & 15) << 2;
            cp_async16(sWs + (uint32_t)(buf * 1152 + row * 72 + q) * 4,
                       W + (size_t)(k0 + row) * ldb + cb + q, true);
        }
    };

    float c[2][4][4];
    #pragma unroll
    for (int mb = 0; mb < 2; mb++)
        #pragma unroll
        for (int nb = 0; nb < 4; nb++)
            #pragma unroll
            for (int j = 0; j < 4; j++) c[mb][nb][j] = 0.f;

    issue(0, 0); cp_commit();

    for (int it = 0; it < 128; it++) {
        int bf = it & 1;
        if (it < 127) { issue(it + 1, bf ^ 1); cp_commit(); cp_wait<1>(); }
        else          { cp_wait<0>(); }
        __syncthreads();

        #pragma unroll
        for (int kk = 0; kk < 16; kk += 8) {
            uint32_t a[2][4], bfr[4][2];
            #pragma unroll
            for (int mb = 0; mb < 2; mb++) {
                int r0 = wm0 + (mb << 4) + gq;
                a[mb][0] = cvt_tf32(As[bf][r0    ][kk + tg]);
                a[mb][1] = cvt_tf32(As[bf][r0 + 8][kk + tg]);
                a[mb][2] = cvt_tf32(As[bf][r0    ][kk + tg + 4]);
                a[mb][3] = cvt_tf32(As[bf][r0 + 8][kk + tg + 4]);
            }
            #pragma unroll
            for (int nb = 0; nb < 4; nb++) {
                int cn = wn0 + (nb << 3) + gq;
                bfr[nb][0] = cvt_tf32(Ws[bf][kk + tg    ][cn]);
                bfr[nb][1] = cvt_tf32(Ws[bf][kk + tg + 4][cn]);
            }
            #pragma unroll
            for (int mb = 0; mb < 2; mb++)
                #pragma unroll
                for (int nb = 0; nb < 4; nb++)
                    mma_tf32(c[mb][nb], a[mb][0], a[mb][1], a[mb][2], a[mb][3],
                             bfr[nb][0], bfr[nb][1]);
        }
        __syncthreads();
    }

    // epilogue: c0,c1 -> (row, 2tg..2tg+1); c2,c3 -> (row+8, ...)
    #pragma unroll
    for (int mb = 0; mb < 2; mb++)
        #pragma unroll
        for (int nb = 0; nb < 4; nb++) {
            int row = m0 + wm0 + (mb << 4) + gq;
            int col = c0 + wn0 + (nb << 3) + (tg << 1);
            *(float2*)(C + (size_t)row * ldc + col)
                = make_float2(c[mb][nb][0], c[mb][nb][1]);
            *(float2*)(C + (size_t)(row + 8) * ldc + col)
                = make_float2(c[mb][nb][2], c[mb][nb][3]);
        }
}

// ---------------- K2: rmsnorm + rope + split (positions computed inline) ----------------
__global__ void normrope_kernel(const float* __restrict__ q_scale,
                                const float* __restrict__ k_scale,
                                const int*   __restrict__ seg,
                                const int*   __restrict__ curp)
{
    int slot = blockIdx.x;
    int m    = blockIdx.y;
    int tid  = threadIdx.x;

    int cbase, type, gi = 0;
    if (slot < 16)      { cbase = slot * 128;               type = 0; }
    else if (slot < 20) { cbase = 2048 + (slot - 16) * 128; type = 1; gi = slot - 16; }
    else                { cbase = 2560 + (slot - 20) * 128; type = 2; gi = slot - 20; }

    float x = g_qkv[m * 3072 + cbase + tid];

    if (type == 2) {   // V: no norm, no rope
        g_vn[(m * G_ + gi) * K_ + tid] = x;
        return;
    }

    __shared__ float wsum[4];
    __shared__ float sx[128];

    float ss = x * x;
    #pragma unroll
    for (int o = 16; o; o >>= 1) ss += __shfl_xor_sync(0xffffffffu, ss, o);
    if ((tid & 31) == 0) wsum[tid >> 5] = ss;
    __syncthreads();
    float var = (wsum[0] + wsum[1] + wsum[2] + wsum[3]) * (1.0f / 128.0f);

    float sc = (type == 0) ? q_scale[tid] : k_scale[tid];
    float xn = x * rsqrtf(var + EPS_) * sc;
    sx[tid] = xn;
    __syncthreads();

    // inline position: pos = cumsum(valid up to this t) - 1 + cur
    int bb = m >> 2, tt = m & 3;
    int csum = 0;
    #pragma unroll
    for (int t = 0; t < T_; t++)
        if (t <= tt) csum += (seg[bb * T_ + t] != 0) ? 1 : 0;
    int pos = csum - 1 + *curp;

    int   j   = tid & 63;
    float fr  = (float)j * (1.0f / 64.0f);
    float ts  = powf(10000.0f, fr);        // accurate pow (large angles)
    float ang = (float)pos / ts;
    float sv, cv;
    sincosf(ang, &sv, &cv);

    float out = (tid < 64) ? (sx[j] * cv - sx[j + 64] * sv)
                           : (sx[j + 64] * cv + sx[j] * sv);

    if (type == 0) g_q [(m * H_ + slot) * K_ + tid] = out;
    else           g_kn[(m * G_ + gi)  * K_ + tid] = out;
}

// ---------------- K3: split flash attention, cp.async pipelined ----------------
// dyn smem floats: QS[2048] | KS[64*132] | VS[64*132] | P[16*65] | M/L/F[48]
#define ATTN_SMEM_FLOATS (2048 + 8448 + 8448 + 1040 + 48)
#define ATTN_SMEM_BYTES  (ATTN_SMEM_FLOATS * 4)

__global__ __launch_bounds__(256, 2) void attn_kernel(
    const float* __restrict__ kc,
    const float* __restrict__ vc,
    const int*   __restrict__ seg,
    const int*   __restrict__ curp)
{
    extern __shared__ float smf[];
    float* QS   = smf;
    float* KS   = smf + 2048;
    float* VS   = KS + 8448;
    float* P    = VS + 8448;
    float* SM_M = P + 1040;
    float* SM_L = SM_M + 16;
    float* SM_F = SM_L + 16;

    int b  = blockIdx.x;
    int g  = blockIdx.y;
    int sp = blockIdx.z;
    int tid  = threadIdx.x;            // 256
    int w    = tid >> 5;
    int lane = tid & 31;

    int cur   = *curp;
    int s_end = cur + T_;

    int sgv0 = seg[b * T_ + 0], sgv1 = seg[b * T_ + 1];
    int sgv2 = seg[b * T_ + 2], sgv3 = seg[b * T_ + 3];

    // inline left-pads
    int start;
    {
        int csum = 0, lp = 0;
        int vv0 = (sgv0 != 0), vv1 = (sgv1 != 0), vv2 = (sgv2 != 0), vv3 = (sgv3 != 0);
        csum += vv0; if (csum == 0) lp++;
        csum += vv1; if (csum == 0) lp++;
        csum += vv2; if (csum == 0) lp++;
        csum += vv3; if (csum == 0) lp++;
        start = lp;
    }

    // chunk range for this split
    int nch  = (s_end + 63) >> 6;
    int per  = (nch + NS - 1) / NS;
    int c_lo = sp * per;
    int c_hi = min(nch, c_lo + per);
    int cst  = max(c_lo, start >> 6);

    uint32_t ksb = (uint32_t)__cvta_generic_to_shared(KS);
    uint32_t vsb = (uint32_t)__cvta_generic_to_shared(VS);

    auto issueK = [&](int ci) {
        int s0c = ci << 6;
        #pragma unroll
        for (int it = 0; it < 8; it++) {
            int idx = tid + (it << 8);
            int row = idx >> 5;
            int c4  = (idx & 31) << 2;
            int s   = s0c + row;
            const float* src; bool p = true;
            if (s < cur)        src = kc + ((((size_t)(b * S_ + s)) * G_ + g) << 7) + c4;
            else if (s < s_end) src = g_kn + (((b * T_ + (s - cur)) * G_ + g) << 7) + c4;
            else              { src = kc; p = false; }
            cp_async16(ksb + (uint32_t)(row * 132 + c4) * 4, src, p);
        }
    };
    auto issueV = [&](int ci) {
        int s0c = ci << 6;
        #pragma unroll
        for (int it = 0; it < 8; it++) {
            int idx = tid + (it << 8);
            int row = idx >> 5;
            int c4  = (idx & 31) << 2;
            int s   = s0c + row;
            const float* src; bool p = true;
            if (s < cur)        src = vc + ((((size_t)(b * S_ + s)) * G_ + g) << 7) + c4;
            else if (s < s_end) src = g_vn + (((b * T_ + (s - cur)) * G_ + g) << 7) + c4;
            else              { src = vc; p = false; }
            cp_async16(vsb + (uint32_t)(row * 132 + c4) * 4, src, p);
        }
    };

    // prologue: stage first chunk (K group, then V group)
    if (cst < c_hi) { issueK(cst); cp_commit(); issueV(cst); cp_commit(); }

    // load the 16 query vectors for this (b,g) (overlaps with cp.async)
    #pragma unroll
    for (int it = 0; it < 2; it++) {
        int idx = tid + (it << 8);
        int q   = idx >> 5;
        int c4  = (idx & 31) << 2;
        int t = q >> 2, rr = q & 3;
        float4 qv = *(const float4*)(g_q + (((b * T_ + t) * H_ + (g * NREP + rr)) << 7) + c4);
        *(float4*)(QS + q * 128 + c4) = qv;
    }
    if (tid < 16) { SM_M[tid] = -3e38f; SM_L[tid] = 0.f; }

    // PV mapping: warp -> 4-query group x 32-row half
    int qg = w >> 1;                    // query group 0..3 (queries 4qg..4qg+3)
    int sh = w & 1;                     // s-half 0/1 (rows 32sh..32sh+31)
    float acc0[4] = {0,0,0,0}, acc1[4] = {0,0,0,0};
    float acc2[4] = {0,0,0,0}, acc3[4] = {0,0,0,0};

    int sl = ((w & 1) << 5) + lane;     // logits: lane's s row within chunk
    int qb = (w >> 1) << 2;             // logits: 4-query group

    __syncthreads();

    for (int ci = cst; ci < c_hi; ci++) {
        int s0 = ci << 6;
        cp_wait<1>();                   // K(ci) complete (V(ci) may be pending)
        __syncthreads();

        // ---- logits: warp computes 4 queries x its 32 s-rows ----
        {
            const float* krow = KS + sl * 132;
            const float* q0 = QS + qb * 128;
            const float* q1 = q0 + 128;
            const float* q2 = q1 + 128;
            const float* q3 = q2 + 128;
            float l0=0.f,l1=0.f,l2=0.f,l3=0.f;
            #pragma unroll
            for (int kk = 0; kk < 128; kk += 4) {
                float4 kv = *(const float4*)(krow + kk);
                float4 a;
                a = *(const float4*)(q0 + kk);
                l0 = fmaf(a.x,kv.x,l0); l0 = fmaf(a.y,kv.y,l0);
                l0 = fmaf(a.z,kv.z,l0); l0 = fmaf(a.w,kv.w,l0);
                a = *(const float4*)(q1 + kk);
                l1 = fmaf(a.x,kv.x,l1); l1 = fmaf(a.y,kv.y,l1);
                l1 = fmaf(a.z,kv.z,l1); l1 = fmaf(a.w,kv.w,l1);
                a = *(const float4*)(q2 + kk);
                l2 = fmaf(a.x,kv.x,l2); l2 = fmaf(a.y,kv.y,l2);
                l2 = fmaf(a.z,kv.z,l2); l2 = fmaf(a.w,kv.w,l2);
                a = *(const float4*)(q3 + kk);
                l3 = fmaf(a.x,kv.x,l3); l3 = fmaf(a.y,kv.y,l3);
                l3 = fmaf(a.z,kv.z,l3); l3 = fmaf(a.w,kv.w,l3);
            }
            int s   = s0 + sl;
            int kvv = (s >= start && s < s_end) ? 1 : 0;
            float lv[4] = {l0, l1, l2, l3};
            int   sgv[4] = {sgv0, sgv1, sgv2, sgv3};
            #pragma unroll
            for (int j = 0; j < 4; j++) {
                int q = qb + j;
                int t = q >> 2;
                bool ok = (s <= cur + t) && (kvv == sgv[t]);
                P[q * 65 + sl] = ok ? lv[j] * SCALE_ : -3e38f;
            }
        }
        __syncthreads();                // P written, KS fully consumed

        if (ci + 1 < c_hi) issueK(ci + 1);
        cp_commit();                    // overlaps softmax + PV

        // ---- online softmax: warp w owns queries {2w, 2w+1} ----
        #pragma unroll
        for (int j = 0; j < 2; j++) {
            int q = (w << 1) + j;
            float v0 = P[q * 65 + lane];
            float v1 = P[q * 65 + lane + 32];
            float cm = fmaxf(v0, v1);
            #pragma unroll
            for (int o = 16; o; o >>= 1) cm = fmaxf(cm, __shfl_xor_sync(0xffffffffu, cm, o));
            float mold = SM_M[q];
            float mnew = fmaxf(mold, cm);
            float e0 = (v0 < -1e37f) ? 0.f : __expf(v0 - mnew);
            float e1 = (v1 < -1e37f) ? 0.f : __expf(v1 - mnew);
            P[q * 65 + lane]      = e0;
            P[q * 65 + lane + 32] = e1;
            float sum = e0 + e1;
            #pragma unroll
            for (int o = 16; o; o >>= 1) sum += __shfl_xor_sync(0xffffffffu, sum, o);
            if (lane == 0) {
                float f = (mold < -1e37f) ? 0.f : __expf(mold - mnew);
                SM_F[q] = f;
                SM_L[q] = SM_L[q] * f + sum;
                SM_M[q] = mnew;
            }
        }
        cp_wait<1>();                   // V(ci) complete (K(ci+1) pending)
        __syncthreads();                // exp P + SM_F visible, VS ready

        // ---- PV: warp = 4 queries x its 32-row half, lane owns 4 dims ----
        {
            int qb4 = qg << 2;
            float f0 = SM_F[qb4 + 0], f1 = SM_F[qb4 + 1];
            float f2 = SM_F[qb4 + 2], f3 = SM_F[qb4 + 3];
            #pragma unroll
            for (int d = 0; d < 4; d++) {
                acc0[d] *= f0; acc1[d] *= f1; acc2[d] *= f2; acc3[d] *= f3;
            }
            const float* p0 = P + (qb4 + 0) * 65 + (sh << 5);
            const float* p1 = P + (qb4 + 1) * 65 + (sh << 5);
            const float* p2 = P + (qb4 + 2) * 65 + (sh << 5);
            const float* p3 = P + (qb4 + 3) * 65 + (sh << 5);
            const float* vbase = VS + (sh << 5) * 132 + (lane << 2);
            #pragma unroll 8
            for (int ssi = 0; ssi < 32; ssi++) {
                float4 vv = *(const float4*)(vbase + ssi * 132);
                float w0 = p0[ssi], w1 = p1[ssi], w2 = p2[ssi], w3 = p3[ssi];
                acc0[0]=fmaf(w0,vv.x,acc0[0]); acc0[1]=fmaf(w0,vv.y,acc0[1]);
                acc0[2]=fmaf(w0,vv.z,acc0[2]); acc0[3]=fmaf(w0,vv.w,acc0[3]);
                acc1[0]=fmaf(w1,vv.x,acc1[0]); acc1[1]=fmaf(w1,vv.y,acc1[1]);
                acc1[2]=fmaf(w1,vv.z,acc1[2]); acc1[3]=fmaf(w1,vv.w,acc1[3]);
                acc2[0]=fmaf(w2,vv.x,acc2[0]); acc2[1]=fmaf(w2,vv.y,acc2[1]);
                acc2[2]=fmaf(w2,vv.z,acc2[2]); acc2[3]=fmaf(w2,vv.w,acc2[3]);
                acc3[0]=fmaf(w3,vv.x,acc3[0]); acc3[1]=fmaf(w3,vv.y,acc3[1]);
                acc3[2]=fmaf(w3,vv.z,acc3[2]); acc3[3]=fmaf(w3,vv.w,acc3[3]);
            }
        }
        __syncthreads();                // VS fully consumed

        if (ci + 1 < c_hi) issueV(ci + 1);
        cp_commit();                    // overlaps next logits
    }

    // ---- merge s-halves and write partials (unnormalized) ----
    {
        int qb4 = qg << 2;
        if (sh == 1) {
            *(float4*)(KS + (qb4+0)*128 + (lane<<2)) = make_float4(acc0[0],acc0[1],acc0[2],acc0[3]);
            *(float4*)(KS + (qb4+1)*128 + (lane<<2)) = make_float4(acc1[0],acc1[1],acc1[2],acc1[3]);
            *(float4*)(KS + (qb4+2)*128 + (lane<<2)) = make_float4(acc2[0],acc2[1],acc2[2],acc2[3]);
            *(float4*)(KS + (qb4+3)*128 + (lane<<2)) = make_float4(acc3[0],acc3[1],acc3[2],acc3[3]);
        }
        __syncthreads();
        if (sh == 0) {
            int pbase = ((b * G_ + g) * NS + sp) * 16;
            float* accs[4] = {acc0, acc1, acc2, acc3};
            #pragma unroll
            for (int j = 0; j < 4; j++) {
                int q = qb4 + j;
                float4 pj = *(const float4*)(KS + q*128 + (lane<<2));
                *(float4*)(g_pacc + (size_t)(pbase + q) * 128 + (lane << 2))
                    = make_float4(accs[j][0]+pj.x, accs[j][1]+pj.y,
                                  accs[j][2]+pj.z, accs[j][3]+pj.w);
                if (lane == 0) {
                    g_pm[pbase + q] = SM_M[q];
                    g_pl[pbase + q] = SM_L[q];
                }
            }
        }
    }
}

// ---------------- K3b: combine split partials ----------------
__global__ void combine_kernel() {
    int bg  = blockIdx.x;              // 0..127 = b*G+g
    int tid = threadIdx.x;             // 256
    int q   = tid >> 4;                // 0..15
    int kb  = (tid & 15) << 3;         // 8 dims
    int base = bg * NS * 16;

    float m = -3e38f;
    #pragma unroll
    for (int s = 0; s < NS; s++) m = fmaxf(m, g_pm[base + s * 16 + q]);

    float lsum = 0.f;
    float o[8];
    #pragma unroll
    for (int j = 0; j < 8; j++) o[j] = 0.f;

    #pragma unroll
    for (int s = 0; s < NS; s++) {
        float ms  = g_pm[base + s * 16 + q];
        float wgt = (ms < -1e37f) ? 0.f : __expf(ms - m);
        lsum += wgt * g_pl[base + s * 16 + q];
        const float* pa = g_pacc + (size_t)(base + s * 16 + q) * 128 + kb;
        float4 x0 = *(const float4*)pa;
        float4 x1 = *(const float4*)(pa + 4);
        o[0] = fmaf(wgt, x0.x, o[0]); o[1] = fmaf(wgt, x0.y, o[1]);
        o[2] = fmaf(wgt, x0.z, o[2]); o[3] = fmaf(wgt, x0.w, o[3]);
        o[4] = fmaf(wgt, x1.x, o[4]); o[5] = fmaf(wgt, x1.y, o[5]);
        o[6] = fmaf(wgt, x1.z, o[6]); o[7] = fmaf(wgt, x1.w, o[7]);
    }
    float inv = (lsum > 0.f) ? (1.0f / lsum) : 0.f;
    int b = bg >> 2, g = bg & 3;
    int t = q >> 2, r = q & 3;
    float* dst = g_attn + (((b * T_ + t) * H_ + g * NREP + r) << 7) + kb;
    *(float4*)dst       = make_float4(o[0]*inv, o[1]*inv, o[2]*inv, o[3]*inv);
    *(float4*)(dst + 4) = make_float4(o[4]*inv, o[5]*inv, o[6]*inv, o[7]*inv);
}

// ---------------- host launch ----------------
extern "C" void kernel_launch(void* const* d_in, const int* in_sizes, int n_in,
                              void* d_out, int out_size) {
    const float* hidden = (const float*)d_in[0];
    const int*   seg    = (const int*)  d_in[1];
    const float* kc     = (const float*)d_in[2];
    const float* vc     = (const float*)d_in[3];
    const float* Wq     = (const float*)d_in[4];
    const float* Wk     = (const float*)d_in[5];
    const float* Wv     = (const float*)d_in[6];
    const float* Wo     = (const float*)d_in[7];
    const float* qsc    = (const float*)d_in[8];
    const float* ksc    = (const float*)d_in[9];
    const int*   curp   = (const int*)  d_in[10];

    (void)in_sizes; (void)n_in; (void)out_size;

    mma_gemm_kernel<<<dim3(48, 2), 128>>>(hidden, Wq, Wk, Wv, nullptr, 3072, 1);
    normrope_kernel<<<dim3(24, 128), 128>>>(qsc, ksc, seg, curp);
    cudaFuncSetAttribute(attn_kernel, cudaFuncAttributeMaxDynamicSharedMemorySize,
                         ATTN_SMEM_BYTES);
    attn_kernel<<<dim3(B_, G_, NS), 256, ATTN_SMEM_BYTES>>>(kc, vc, seg, curp);
    combine_kernel<<<128, 256>>>();
    mma_gemm_kernel<<<dim3(32, 2), 128>>>(nullptr, Wo, Wo, Wo, (float*)d_out, 2048, 0);
}

// round 13
// speedup vs baseline: 3.3683x; 1.5702x over previous
#include <cuda_runtime.h>
#include <cuda_bf16.h>
#include <stdint.h>
#include <stddef.h>

// Problem constants
#define B_   32
#define T_   4
#define D_   2048
#define H_   16
#define G_   4
#define K_   128
#define S_   4096
#define NREP 4
#define NS   4            // sequence splits for attention
#define SCALE_ 0.08838834764831845f   // K^-0.5
#define EPS_   1e-6f

// ---------------- device scratch (no allocations allowed) ----------------
__device__ __align__(16) float g_qkv[128 * 3072];       // raw projections
__device__ __align__(16) float g_q  [128 * H_ * K_];    // post norm+rope
__device__ __align__(16) float g_kn [128 * G_ * K_];    // new K rows
__device__ __align__(16) float g_vn [128 * G_ * K_];    // new V rows
__device__ __align__(16) float g_attn[128 * H_ * K_];   // attention out
// split-attention partials
__device__ __align__(16) float g_pacc[B_ * G_ * NS * 16 * 128];
__device__ float g_pm  [B_ * G_ * NS * 16];
__device__ float g_pl  [B_ * G_ * NS * 16];

// ---------------- cp.async helpers ----------------
__device__ __forceinline__ void cp_async16(uint32_t dst, const void* src, bool p) {
    asm volatile("cp.async.cg.shared.global [%0], [%1], 16, %2;\n"
                 :: "r"(dst), "l"(src), "r"(p ? 16 : 0));
}
__device__ __forceinline__ void cp_commit() {
    asm volatile("cp.async.commit_group;\n" ::);
}
template<int N> __device__ __forceinline__ void cp_wait() {
    asm volatile("cp.async.wait_group %0;\n" :: "n"(N));
}

// ---------------- tf32 mma helpers ----------------
__device__ __forceinline__ uint32_t cvt_tf32(float x) {
    uint32_t u;
    asm("cvt.rna.tf32.f32 %0, %1;" : "=r"(u) : "f"(x));
    return u;
}
__device__ __forceinline__ void mma_tf32(float c[4],
    uint32_t a0, uint32_t a1, uint32_t a2, uint32_t a3,
    uint32_t b0, uint32_t b1)
{
    asm volatile(
        "mma.sync.aligned.m16n8k8.row.col.f32.tf32.tf32.f32 "
        "{%0,%1,%2,%3}, {%4,%5,%6,%7}, {%8,%9}, {%0,%1,%2,%3};\n"
        : "+f"(c[0]), "+f"(c[1]), "+f"(c[2]), "+f"(c[3])
        : "r"(a0), "r"(a1), "r"(a2), "r"(a3), "r"(b0), "r"(b1));
}

// ---------------- GEMM: tf32 mma, 64x64 tile, 128 thr, cp.async 4-stage ------
__global__ __launch_bounds__(128) void mma_gemm_kernel(
    const float* __restrict__ A_,
    const float* __restrict__ W0, const float* __restrict__ W1,
    const float* __restrict__ W2,
    float* __restrict__ C_, int ldc, int qkv)
{
    __shared__ alignas(16) float As[4][64][20];   // [buf][m][k], stride 20
    __shared__ alignas(16) float Ws[4][16][72];   // [buf][k][n], stride 72

    const float* A = A_ ? A_ : (const float*)g_attn;
    float*       C = C_ ? C_ : (float*)g_qkv;

    int c0 = blockIdx.x * 64;
    const float* W; int ldb, cb;
    if (qkv) {
        if (c0 < 2048)      { W = W0; ldb = 2048; cb = c0; }
        else if (c0 < 2560) { W = W1; ldb = 512;  cb = c0 - 2048; }
        else                { W = W2; ldb = 512;  cb = c0 - 2560; }
    } else                  { W = W0; ldb = 2048; cb = c0; }

    int m0   = blockIdx.y * 64;
    int tid  = threadIdx.x;           // 128
    int wid  = tid >> 5;
    int lane = tid & 31;
    int gq   = lane >> 2;             // group id 0..7
    int tg   = lane & 3;              // thread-in-group 0..3
    int wm0  = (wid >> 1) << 5;       // warp m offset 0/32
    int wn0  = (wid & 1) << 5;        // warp n offset 0/32

    uint32_t sAs = (uint32_t)__cvta_generic_to_shared(&As[0][0][0]);
    uint32_t sWs = (uint32_t)__cvta_generic_to_shared(&Ws[0][0][0]);

    auto issue = [&](int it, int buf) {
        int k0 = it << 4;
        #pragma unroll
        for (int j = 0; j < 2; j++) {                // A: 64 rows x 16 cols
            int idx = tid + (j << 7);                // 0..255 float4
            int row = idx >> 2, q = (idx & 3) << 2;
            cp_async16(sAs + (uint32_t)(buf * 1280 + row * 20 + q) * 4,
                       A + (size_t)(m0 + row) * 2048 + k0 + q, true);
        }
        #pragma unroll
        for (int j = 0; j < 2; j++) {                // W: 16 rows x 64 cols
            int idx = tid + (j << 7);                // 0..255 float4
            int row = idx >> 4, q = (idx & 15) << 2;
            cp_async16(sWs + (uint32_t)(buf * 1152 + row * 72 + q) * 4,
                       W + (size_t)(k0 + row) * ldb + cb + q, true);
        }
    };

    float c[2][4][4];
    #pragma unroll
    for (int mb = 0; mb < 2; mb++)
        #pragma unroll
        for (int nb = 0; nb < 4; nb++)
            #pragma unroll
            for (int j = 0; j < 4; j++) c[mb][nb][j] = 0.f;

    issue(0, 0); cp_commit();
    issue(1, 1); cp_commit();
    issue(2, 2); cp_commit();

    for (int it = 0; it < 128; it++) {
        int bf = it & 3;
        cp_wait<2>();
        __syncthreads();

        #pragma unroll
        for (int kk = 0; kk < 16; kk += 8) {
            uint32_t a[2][4], bfr[4][2];
            #pragma unroll
            for (int mb = 0; mb < 2; mb++) {
                int r0 = wm0 + (mb << 4) + gq;
                a[mb][0] = cvt_tf32(As[bf][r0    ][kk + tg]);
                a[mb][1] = cvt_tf32(As[bf][r0 + 8][kk + tg]);
                a[mb][2] = cvt_tf32(As[bf][r0    ][kk + tg + 4]);
                a[mb][3] = cvt_tf32(As[bf][r0 + 8][kk + tg + 4]);
            }
            #pragma unroll
            for (int nb = 0; nb < 4; nb++) {
                int cn = wn0 + (nb << 3) + gq;
                bfr[nb][0] = cvt_tf32(Ws[bf][kk + tg    ][cn]);
                bfr[nb][1] = cvt_tf32(Ws[bf][kk + tg + 4][cn]);
            }
            #pragma unroll
            for (int mb = 0; mb < 2; mb++)
                #pragma unroll
                for (int nb = 0; nb < 4; nb++)
                    mma_tf32(c[mb][nb], a[mb][0], a[mb][1], a[mb][2], a[mb][3],
                             bfr[nb][0], bfr[nb][1]);
        }
        __syncthreads();
        if (it + 3 < 128) issue(it + 3, (it + 3) & 3);
        cp_commit();
    }

    #pragma unroll
    for (int mb = 0; mb < 2; mb++)
        #pragma unroll
        for (int nb = 0; nb < 4; nb++) {
            int row = m0 + wm0 + (mb << 4) + gq;
            int col = c0 + wn0 + (nb << 3) + (tg << 1);
            *(float2*)(C + (size_t)row * ldc + col)
                = make_float2(c[mb][nb][0], c[mb][nb][1]);
            *(float2*)(C + (size_t)(row + 8) * ldc + col)
                = make_float2(c[mb][nb][2], c[mb][nb][3]);
        }
}

// ---------------- K2: rmsnorm + rope + split (positions computed inline) ----------------
__global__ void normrope_kernel(const float* __restrict__ q_scale,
                                const float* __restrict__ k_scale,
                                const int*   __restrict__ seg,
                                const int*   __restrict__ curp)
{
    int slot = blockIdx.x;
    int m    = blockIdx.y;
    int tid  = threadIdx.x;

    int cbase, type, gi = 0;
    if (slot < 16)      { cbase = slot * 128;               type = 0; }
    else if (slot < 20) { cbase = 2048 + (slot - 16) * 128; type = 1; gi = slot - 16; }
    else                { cbase = 2560 + (slot - 20) * 128; type = 2; gi = slot - 20; }

    float x = g_qkv[m * 3072 + cbase + tid];

    if (type == 2) {   // V: no norm, no rope
        g_vn[(m * G_ + gi) * K_ + tid] = x;
        return;
    }

    __shared__ float wsum[4];
    __shared__ float sx[128];

    float ss = x * x;
    #pragma unroll
    for (int o = 16; o; o >>= 1) ss += __shfl_xor_sync(0xffffffffu, ss, o);
    if ((tid & 31) == 0) wsum[tid >> 5] = ss;
    __syncthreads();
    float var = (wsum[0] + wsum[1] + wsum[2] + wsum[3]) * (1.0f / 128.0f);

    float sc = (type == 0) ? q_scale[tid] : k_scale[tid];
    float xn = x * rsqrtf(var + EPS_) * sc;
    sx[tid] = xn;
    __syncthreads();

    int bb = m >> 2, tt = m & 3;
    int csum = 0;
    #pragma unroll
    for (int t = 0; t < T_; t++)
        if (t <= tt) csum += (seg[bb * T_ + t] != 0) ? 1 : 0;
    int pos = csum - 1 + *curp;

    int   j   = tid & 63;
    float fr  = (float)j * (1.0f / 64.0f);
    float ts  = powf(10000.0f, fr);        // accurate pow (large angles)
    float ang = (float)pos / ts;
    float sv, cv;
    sincosf(ang, &sv, &cv);

    float out = (tid < 64) ? (sx[j] * cv - sx[j + 64] * sv)
                           : (sx[j + 64] * cv + sx[j] * sv);

    if (type == 0) g_q [(m * H_ + slot) * K_ + tid] = out;
    else           g_kn[(m * G_ + gi)  * K_ + tid] = out;
}

// ---------------- K3: split flash attention, tf32 mma, cp.async pipelined ----
// dyn smem floats: QS[2048] | KS[64*132] | VS[64*132] | P[16*68] | M/L/F[48]
#define ATTN_SMEM_FLOATS (2048 + 8448 + 8448 + 1088 + 48)
#define ATTN_SMEM_BYTES  (ATTN_SMEM_FLOATS * 4)

__global__ __launch_bounds__(256, 2) void attn_kernel(
    const float* __restrict__ kc,
    const float* __restrict__ vc,
    const int*   __restrict__ seg,
    const int*   __restrict__ curp)
{
    extern __shared__ float smf[];
    float* QS   = smf;
    float* KS   = smf + 2048;
    float* VS   = KS + 8448;
    float* P    = VS + 8448;
    float* SM_M = P + 1088;
    float* SM_L = SM_M + 16;
    float* SM_F = SM_L + 16;

    int b  = blockIdx.x;
    int g  = blockIdx.y;
    int sp = blockIdx.z;
    int tid  = threadIdx.x;            // 256
    int w    = tid >> 5;
    int lane = tid & 31;
    int gq   = lane >> 2;              // mma group id 0..7
    int tg   = lane & 3;               // thread-in-group 0..3

    int cur   = *curp;
    int s_end = cur + T_;

    int sgv0 = seg[b * T_ + 0], sgv1 = seg[b * T_ + 1];
    int sgv2 = seg[b * T_ + 2], sgv3 = seg[b * T_ + 3];

    // inline left-pads
    int start;
    {
        int csum = 0, lp = 0;
        csum += (sgv0 != 0); if (csum == 0) lp++;
        csum += (sgv1 != 0); if (csum == 0) lp++;
        csum += (sgv2 != 0); if (csum == 0) lp++;
        csum += (sgv3 != 0); if (csum == 0) lp++;
        start = lp;
    }

    // chunk range for this split
    int nch  = (s_end + 63) >> 6;
    int per  = (nch + NS - 1) / NS;
    int c_lo = sp * per;
    int c_hi = min(nch, c_lo + per);
    int cst  = max(c_lo, start >> 6);

    uint32_t ksb = (uint32_t)__cvta_generic_to_shared(KS);
    uint32_t vsb = (uint32_t)__cvta_generic_to_shared(VS);

    auto issueK = [&](int ci) {
        int s0c = ci << 6;
        #pragma unroll
        for (int it = 0; it < 8; it++) {
            int idx = tid + (it << 8);
            int row = idx >> 5;
            int c4  = (idx & 31) << 2;
            int s   = s0c + row;
            const float* src; bool p = true;
            if (s < cur)        src = kc + ((((size_t)(b * S_ + s)) * G_ + g) << 7) + c4;
            else if (s < s_end) src = g_kn + (((b * T_ + (s - cur)) * G_ + g) << 7) + c4;
            else              { src = kc; p = false; }
            cp_async16(ksb + (uint32_t)(row * 132 + c4) * 4, src, p);
        }
    };
    auto issueV = [&](int ci) {
        int s0c = ci << 6;
        #pragma unroll
        for (int it = 0; it < 8; it++) {
            int idx = tid + (it << 8);
            int row = idx >> 5;
            int c4  = (idx & 31) << 2;
            int s   = s0c + row;
            const float* src; bool p = true;
            if (s < cur)        src = vc + ((((size_t)(b * S_ + s)) * G_ + g) << 7) + c4;
            else if (s < s_end) src = g_vn + (((b * T_ + (s - cur)) * G_ + g) << 7) + c4;
            else              { src = vc; p = false; }
            cp_async16(vsb + (uint32_t)(row * 132 + c4) * 4, src, p);
        }
    };

    // prologue: stage first chunk (K group, then V group)
    if (cst < c_hi) { issueK(cst); cp_commit(); issueV(cst); cp_commit(); }

    // stage the 16 query vectors into QS (overlaps with cp.async)
    #pragma unroll
    for (int it = 0; it < 2; it++) {
        int idx = tid + (it << 8);
        int q   = idx >> 5;
        int c4  = (idx & 31) << 2;
        int t = q >> 2, rr = q & 3;
        float4 qv = *(const float4*)(g_q + (((b * T_ + t) * H_ + (g * NREP + rr)) << 7) + c4);
        *(float4*)(QS + q * 128 + c4) = qv;
    }
    if (tid < 16) { SM_M[tid] = -3e38f; SM_L[tid] = 0.f; }
    __syncthreads();

    // convert Q fragments to tf32 registers once (shared by all chunks/warps)
    uint32_t qa[16][4];
    #pragma unroll
    for (int ks = 0; ks < 16; ks++) {
        int col = (ks << 3) + tg;
        qa[ks][0] = cvt_tf32(QS[ gq      * 128 + col]);
        qa[ks][1] = cvt_tf32(QS[(gq + 8) * 128 + col]);
        qa[ks][2] = cvt_tf32(QS[ gq      * 128 + col + 4]);
        qa[ks][3] = cvt_tf32(QS[(gq + 8) * 128 + col + 4]);
    }

    // PV accumulators: warp w owns dims [16w, 16w+16), all 16 queries
    float oc[2][4];
    #pragma unroll
    for (int t = 0; t < 2; t++)
        #pragma unroll
        for (int j = 0; j < 4; j++) oc[t][j] = 0.f;

    int n0 = w << 3;                    // logits: this warp's 8 keys

    for (int ci = cst; ci < c_hi; ci++) {
        int s0 = ci << 6;
        cp_wait<1>();                   // K(ci) complete (V(ci) may be pending)
        __syncthreads();

        // ---- logits: warp computes 16 queries x its 8 keys via mma ----
        {
            float sc_[4] = {0.f, 0.f, 0.f, 0.f};
            #pragma unroll
            for (int ks = 0; ks < 16; ks++) {
                int col = (ks << 3) + tg;
                uint32_t b0 = cvt_tf32(KS[(n0 + gq) * 132 + col]);
                uint32_t b1 = cvt_tf32(KS[(n0 + gq) * 132 + col + 4]);
                mma_tf32(sc_, qa[ks][0], qa[ks][1], qa[ks][2], qa[ks][3], b0, b1);
            }
            // mask + write to P: c0,c1 -> row gq cols 2tg,2tg+1; c2,c3 -> row gq+8
            int sl0 = n0 + (tg << 1);
            int sgl0 = s0 + sl0, sgl1 = sgl0 + 1;
            int kv0 = (sgl0 >= start && sgl0 < s_end) ? 1 : 0;
            int kv1 = (sgl1 >= start && sgl1 < s_end) ? 1 : 0;
            int sgv[4] = {sgv0, sgv1, sgv2, sgv3};
            int t0 = gq >> 2, t1 = (gq + 8) >> 2;
            bool ok00 = (sgl0 <= cur + t0) && (kv0 == sgv[t0]);
            bool ok01 = (sgl1 <= cur + t0) && (kv1 == sgv[t0]);
            bool ok10 = (sgl0 <= cur + t1) && (kv0 == sgv[t1]);
            bool ok11 = (sgl1 <= cur + t1) && (kv1 == sgv[t1]);
            P[ gq      * 68 + sl0    ] = ok00 ? sc_[0] * SCALE_ : -3e38f;
            P[ gq      * 68 + sl0 + 1] = ok01 ? sc_[1] * SCALE_ : -3e38f;
            P[(gq + 8) * 68 + sl0    ] = ok10 ? sc_[2] * SCALE_ : -3e38f;
            P[(gq + 8) * 68 + sl0 + 1] = ok11 ? sc_[3] * SCALE_ : -3e38f;
        }
        __syncthreads();                // P written, KS fully consumed

        if (ci + 1 < c_hi) issueK(ci + 1);
        cp_commit();                    // overlaps softmax + PV

        // ---- online softmax: warp w owns queries {2w, 2w+1} ----
        #pragma unroll
        for (int j = 0; j < 2; j++) {
            int q = (w << 1) + j;
            float v0 = P[q * 68 + lane];
            float v1 = P[q * 68 + lane + 32];
            float cm = fmaxf(v0, v1);
            #pragma unroll
            for (int o = 16; o; o >>= 1) cm = fmaxf(cm, __shfl_xor_sync(0xffffffffu, cm, o));
            float mold = SM_M[q];
            float mnew = fmaxf(mold, cm);
            float e0 = (v0 < -1e37f) ? 0.f : __expf(v0 - mnew);
            float e1 = (v1 < -1e37f) ? 0.f : __expf(v1 - mnew);
            P[q * 68 + lane]      = e0;
            P[q * 68 + lane + 32] = e1;
            float sum = e0 + e1;
            #pragma unroll
            for (int o = 16; o; o >>= 1) sum += __shfl_xor_sync(0xffffffffu, sum, o);
            if (lane == 0) {
                float f = (mold < -1e37f) ? 0.f : __expf(mold - mnew);
                SM_F[q] = f;
                SM_L[q] = SM_L[q] * f + sum;
                SM_M[q] = mnew;
            }
        }
        cp_wait<1>();                   // V(ci) complete (K(ci+1) pending)
        __syncthreads();                // exp P + SM_F visible, VS ready

        // ---- PV: warp w, dims 16w..16w+15, all queries, via mma ----
        {
            float f0 = SM_F[gq], f1 = SM_F[gq + 8];
            #pragma unroll
            for (int t = 0; t < 2; t++) {
                oc[t][0] *= f0; oc[t][1] *= f0;
                oc[t][2] *= f1; oc[t][3] *= f1;
            }
            #pragma unroll
            for (int ks = 0; ks < 8; ks++) {
                int kr = (ks << 3) + tg;
                uint32_t a0 = cvt_tf32(P[ gq      * 68 + kr]);
                uint32_t a1 = cvt_tf32(P[(gq + 8) * 68 + kr]);
                uint32_t a2 = cvt_tf32(P[ gq      * 68 + kr + 4]);
                uint32_t a3 = cvt_tf32(P[(gq + 8) * 68 + kr + 4]);
                #pragma unroll
                for (int t = 0; t < 2; t++) {
                    int nd = (w << 4) + (t << 3) + gq;
                    uint32_t b0 = cvt_tf32(VS[kr * 132 + nd]);
                    uint32_t b1 = cvt_tf32(VS[(kr + 4) * 132 + nd]);
                    mma_tf32(oc[t], a0, a1, a2, a3, b0, b1);
                }
            }
        }
        __syncthreads();                // VS fully consumed

        if (ci + 1 < c_hi) issueV(ci + 1);
        cp_commit();                    // overlaps next logits
    }

    // ---- write partials (unnormalized) ----
    {
        int pbase = ((b * G_ + g) * NS + sp) * 16;
        #pragma unroll
        for (int t = 0; t < 2; t++) {
            int col = (w << 4) + (t << 3) + (tg << 1);
            *(float2*)(g_pacc + (size_t)(pbase + gq) * 128 + col)
                = make_float2(oc[t][0], oc[t][1]);
            *(float2*)(g_pacc + (size_t)(pbase + gq + 8) * 128 + col)
                = make_float2(oc[t][2], oc[t][3]);
        }
        if (tid < 16) {
            g_pm[pbase + tid] = SM_M[tid];
            g_pl[pbase + tid] = SM_L[tid];
        }
    }
}

// ---------------- K3b: combine split partials ----------------
__global__ void combine_kernel() {
    int bg  = blockIdx.x;              // 0..127 = b*G+g
    int tid = threadIdx.x;             // 256
    int q   = tid >> 4;                // 0..15
    int kb  = (tid & 15) << 3;         // 8 dims
    int base = bg * NS * 16;

    float m = -3e38f;
    #pragma unroll
    for (int s = 0; s < NS; s++) m = fmaxf(m, g_pm[base + s * 16 + q]);

    float lsum = 0.f;
    float o[8];
    #pragma unroll
    for (int j = 0; j < 8; j++) o[j] = 0.f;

    #pragma unroll
    for (int s = 0; s < NS; s++) {
        float ms  = g_pm[base + s * 16 + q];
        float wgt = (ms < -1e37f) ? 0.f : __expf(ms - m);
        lsum += wgt * g_pl[base + s * 16 + q];
        const float* pa = g_pacc + (size_t)(base + s * 16 + q) * 128 + kb;
        float4 x0 = *(const float4*)pa;
        float4 x1 = *(const float4*)(pa + 4);
        o[0] = fmaf(wgt, x0.x, o[0]); o[1] = fmaf(wgt, x0.y, o[1]);
        o[2] = fmaf(wgt, x0.z, o[2]); o[3] = fmaf(wgt, x0.w, o[3]);
        o[4] = fmaf(wgt, x1.x, o[4]); o[5] = fmaf(wgt, x1.y, o[5]);
        o[6] = fmaf(wgt, x1.z, o[6]); o[7] = fmaf(wgt, x1.w, o[7]);
    }
    float inv = (lsum > 0.f) ? (1.0f / lsum) : 0.f;
    int b = bg >> 2, g = bg & 3;
    int t = q >> 2, r = q & 3;
    float* dst = g_attn + (((b * T_ + t) * H_ + g * NREP + r) << 7) + kb;
    *(float4*)dst       = make_float4(o[0]*inv, o[1]*inv, o[2]*inv, o[3]*inv);
    *(float4*)(dst + 4) = make_float4(o[4]*inv, o[5]*inv, o[6]*inv, o[7]*inv);
}

// ---------------- host launch ----------------
extern "C" void kernel_launch(void* const* d_in, const int* in_sizes, int n_in,
                              void* d_out, int out_size) {
    const float* hidden = (const float*)d_in[0];
    const int*   seg    = (const int*)  d_in[1];
    const float* kc     = (const float*)d_in[2];
    const float* vc     = (const float*)d_in[3];
    const float* Wq     = (const float*)d_in[4];
    const float* Wk     = (const float*)d_in[5];
    const float* Wv     = (const float*)d_in[6];
    const float* Wo     = (const float*)d_in[7];
    const float* qsc    = (const float*)d_in[8];
    const float* ksc    = (const float*)d_in[9];
    const int*   curp   = (const int*)  d_in[10];

    (void)in_sizes; (void)n_in; (void)out_size;

    mma_gemm_kernel<<<dim3(48, 2), 128>>>(hidden, Wq, Wk, Wv, nullptr, 3072, 1);
    normrope_kernel<<<dim3(24, 128), 128>>>(qsc, ksc, seg, curp);
    cudaFuncSetAttribute(attn_kernel, cudaFuncAttributeMaxDynamicSharedMemorySize,
                         ATTN_SMEM_BYTES);
    attn_kernel<<<dim3(B_, G_, NS), 256, ATTN_SMEM_BYTES>>>(kc, vc, seg, curp);
    combine_kernel<<<128, 256>>>();
    mma_gemm_kernel<<<dim3(32, 2), 128>>>(nullptr, Wo, Wo, Wo, (float*)d_out, 2048, 0);
}

// round 14
// speedup vs baseline: 4.1466x; 1.2311x over previous
#include <cuda_runtime.h>
#include <cuda_bf16.h>
#include <stdint.h>
#include <stddef.h>

// Problem constants
#define B_   32
#define T_   4
#define D_   2048
#define H_   16
#define G_   4
#define K_   128
#define S_   4096
#define NREP 4
#define NS   7            // sequence splits for attention (49 chunks / 7 = balanced)
#define SCALE_ 0.08838834764831845f   // K^-0.5
#define EPS_   1e-6f

// ---------------- device scratch (no allocations allowed) ----------------
__device__ __align__(16) float g_qkvp[2 * 128 * 3072];  // QKV split-K partials
__device__ __align__(16) float g_wop [4 * 128 * 2048];  // Wo split-K partials
__device__ __align__(16) float g_q  [128 * H_ * K_];    // post norm+rope
__device__ __align__(16) float g_kn [128 * G_ * K_];    // new K rows
__device__ __align__(16) float g_vn [128 * G_ * K_];    // new V rows
__device__ __align__(16) float g_attn[128 * H_ * K_];   // attention out
// split-attention partials
__device__ __align__(16) float g_pacc[B_ * G_ * NS * 16 * 128];
__device__ float g_pm  [B_ * G_ * NS * 16];
__device__ float g_pl  [B_ * G_ * NS * 16];

// ---------------- cp.async helpers ----------------
__device__ __forceinline__ void cp_async16(uint32_t dst, const void* src, bool p) {
    asm volatile("cp.async.cg.shared.global [%0], [%1], 16, %2;\n"
                 :: "r"(dst), "l"(src), "r"(p ? 16 : 0));
}
__device__ __forceinline__ void cp_commit() {
    asm volatile("cp.async.commit_group;\n" ::);
}
template<int N> __device__ __forceinline__ void cp_wait() {
    asm volatile("cp.async.wait_group %0;\n" :: "n"(N));
}

// ---------------- tf32 mma helpers ----------------
__device__ __forceinline__ uint32_t cvt_tf32(float x) {
    uint32_t u;
    asm("cvt.rna.tf32.f32 %0, %1;" : "=r"(u) : "f"(x));
    return u;
}
__device__ __forceinline__ void mma_tf32(float c[4],
    uint32_t a0, uint32_t a1, uint32_t a2, uint32_t a3,
    uint32_t b0, uint32_t b1)
{
    asm volatile(
        "mma.sync.aligned.m16n8k8.row.col.f32.tf32.tf32.f32 "
        "{%0,%1,%2,%3}, {%4,%5,%6,%7}, {%8,%9}, {%0,%1,%2,%3};\n"
        : "+f"(c[0]), "+f"(c[1]), "+f"(c[2]), "+f"(c[3])
        : "r"(a0), "r"(a1), "r"(a2), "r"(a3), "r"(b0), "r"(b1));
}

// ---------------- GEMM: tf32 mma, 64x64 tile, split-K via blockIdx.z ---------
// qkv=1: C = g_qkvp + z*128*3072 (ldc=3072), A = hidden, cols select Wq/Wk/Wv
// qkv=0: C = g_wop  + z*128*2048 (ldc=2048), A = g_attn, W0 = Wo
template<int KIT>
__global__ __launch_bounds__(128) void mma_gemm_kernel(
    const float* __restrict__ A_,
    const float* __restrict__ W0, const float* __restrict__ W1,
    const float* __restrict__ W2,
    int ldc, int qkv)
{
    __shared__ alignas(16) float As[4][64][20];   // [buf][m][k], stride 20
    __shared__ alignas(16) float Ws[4][16][72];   // [buf][k][n], stride 72

    const float* A = qkv ? A_ : (const float*)g_attn;
    float*       C = qkv ? (g_qkvp + (size_t)blockIdx.z * 128 * 3072)
                         : (g_wop  + (size_t)blockIdx.z * 128 * 2048);
    int kbase = blockIdx.z * KIT;

    int c0 = blockIdx.x * 64;
    const float* W; int ldb, cb;
    if (qkv) {
        if (c0 < 2048)      { W = W0; ldb = 2048; cb = c0; }
        else if (c0 < 2560) { W = W1; ldb = 512;  cb = c0 - 2048; }
        else                { W = W2; ldb = 512;  cb = c0 - 2560; }
    } else                  { W = W0; ldb = 2048; cb = c0; }

    int m0   = blockIdx.y * 64;
    int tid  = threadIdx.x;           // 128
    int wid  = tid >> 5;
    int lane = tid & 31;
    int gq   = lane >> 2;             // group id 0..7
    int tg   = lane & 3;              // thread-in-group 0..3
    int wm0  = (wid >> 1) << 5;       // warp m offset 0/32
    int wn0  = (wid & 1) << 5;        // warp n offset 0/32

    uint32_t sAs = (uint32_t)__cvta_generic_to_shared(&As[0][0][0]);
    uint32_t sWs = (uint32_t)__cvta_generic_to_shared(&Ws[0][0][0]);

    auto issue = [&](int it, int buf) {
        int k0 = (kbase + it) << 4;
        #pragma unroll
        for (int j = 0; j < 2; j++) {                // A: 64 rows x 16 cols
            int idx = tid + (j << 7);                // 0..255 float4
            int row = idx >> 2, q = (idx & 3) << 2;
            cp_async16(sAs + (uint32_t)(buf * 1280 + row * 20 + q) * 4,
                       A + (size_t)(m0 + row) * 2048 + k0 + q, true);
        }
        #pragma unroll
        for (int j = 0; j < 2; j++) {                // W: 16 rows x 64 cols
            int idx = tid + (j << 7);                // 0..255 float4
            int row = idx >> 4, q = (idx & 15) << 2;
            cp_async16(sWs + (uint32_t)(buf * 1152 + row * 72 + q) * 4,
                       W + (size_t)(k0 + row) * ldb + cb + q, true);
        }
    };

    float c[2][4][4];
    #pragma unroll
    for (int mb = 0; mb < 2; mb++)
        #pragma unroll
        for (int nb = 0; nb < 4; nb++)
            #pragma unroll
            for (int j = 0; j < 4; j++) c[mb][nb][j] = 0.f;

    issue(0, 0); cp_commit();
    issue(1, 1); cp_commit();
    issue(2, 2); cp_commit();

    for (int it = 0; it < KIT; it++) {
        int bf = it & 3;
        cp_wait<2>();
        __syncthreads();

        #pragma unroll
        for (int kk = 0; kk < 16; kk += 8) {
            uint32_t a[2][4], bfr[4][2];
            #pragma unroll
            for (int mb = 0; mb < 2; mb++) {
                int r0 = wm0 + (mb << 4) + gq;
                a[mb][0] = cvt_tf32(As[bf][r0    ][kk + tg]);
                a[mb][1] = cvt_tf32(As[bf][r0 + 8][kk + tg]);
                a[mb][2] = cvt_tf32(As[bf][r0    ][kk + tg + 4]);
                a[mb][3] = cvt_tf32(As[bf][r0 + 8][kk + tg + 4]);
            }
            #pragma unroll
            for (int nb = 0; nb < 4; nb++) {
                int cn = wn0 + (nb << 3) + gq;
                bfr[nb][0] = cvt_tf32(Ws[bf][kk + tg    ][cn]);
                bfr[nb][1] = cvt_tf32(Ws[bf][kk + tg + 4][cn]);
            }
            #pragma unroll
            for (int mb = 0; mb < 2; mb++)
                #pragma unroll
                for (int nb = 0; nb < 4; nb++)
                    mma_tf32(c[mb][nb], a[mb][0], a[mb][1], a[mb][2], a[mb][3],
                             bfr[nb][0], bfr[nb][1]);
        }
        __syncthreads();
        if (it + 3 < KIT) issue(it + 3, (it + 3) & 3);
        cp_commit();
    }

    #pragma unroll
    for (int mb = 0; mb < 2; mb++)
        #pragma unroll
        for (int nb = 0; nb < 4; nb++) {
            int row = m0 + wm0 + (mb << 4) + gq;
            int col = c0 + wn0 + (nb << 3) + (tg << 1);
            *(float2*)(C + (size_t)row * ldc + col)
                = make_float2(c[mb][nb][0], c[mb][nb][1]);
            *(float2*)(C + (size_t)(row + 8) * ldc + col)
                = make_float2(c[mb][nb][2], c[mb][nb][3]);
        }
}

// ---------------- Wo split-K reduce: d_out = sum of 4 partials ----------------
__global__ void wo_reduce_kernel(float* __restrict__ out) {
    int idx = (blockIdx.x * 256 + threadIdx.x) << 2;   // float4 index space
    float4 a = *(const float4*)(g_wop + idx);
    float4 b = *(const float4*)(g_wop + 262144 + idx);
    float4 c = *(const float4*)(g_wop + 524288 + idx);
    float4 d = *(const float4*)(g_wop + 786432 + idx);
    *(float4*)(out + idx) = make_float4(a.x + b.x + c.x + d.x,
                                        a.y + b.y + c.y + d.y,
                                        a.z + b.z + c.z + d.z,
                                        a.w + b.w + c.w + d.w);
}

// ---------------- K2: rmsnorm + rope + split (sums QKV split-K partials) -----
__global__ void normrope_kernel(const float* __restrict__ q_scale,
                                const float* __restrict__ k_scale,
                                const int*   __restrict__ seg,
                                const int*   __restrict__ curp)
{
    int slot = blockIdx.x;
    int m    = blockIdx.y;
    int tid  = threadIdx.x;

    int cbase, type, gi = 0;
    if (slot < 16)      { cbase = slot * 128;               type = 0; }
    else if (slot < 20) { cbase = 2048 + (slot - 16) * 128; type = 1; gi = slot - 16; }
    else                { cbase = 2560 + (slot - 20) * 128; type = 2; gi = slot - 20; }

    int idx = m * 3072 + cbase + tid;
    float x = g_qkvp[idx] + g_qkvp[393216 + idx];

    if (type == 2) {   // V: no norm, no rope
        g_vn[(m * G_ + gi) * K_ + tid] = x;
        return;
    }

    __shared__ float wsum[4];
    __shared__ float sx[128];

    float ss = x * x;
    #pragma unroll
    for (int o = 16; o; o >>= 1) ss += __shfl_xor_sync(0xffffffffu, ss, o);
    if ((tid & 31) == 0) wsum[tid >> 5] = ss;
    __syncthreads();
    float var = (wsum[0] + wsum[1] + wsum[2] + wsum[3]) * (1.0f / 128.0f);

    float sc = (type == 0) ? q_scale[tid] : k_scale[tid];
    float xn = x * rsqrtf(var + EPS_) * sc;
    sx[tid] = xn;
    __syncthreads();

    int bb = m >> 2, tt = m & 3;
    int csum = 0;
    #pragma unroll
    for (int t = 0; t < T_; t++)
        if (t <= tt) csum += (seg[bb * T_ + t] != 0) ? 1 : 0;
    int pos = csum - 1 + *curp;

    int   j   = tid & 63;
    float fr  = (float)j * (1.0f / 64.0f);
    float ts  = powf(10000.0f, fr);        // accurate pow (large angles)
    float ang = (float)pos / ts;
    float sv, cv;
    sincosf(ang, &sv, &cv);

    float out = (tid < 64) ? (sx[j] * cv - sx[j + 64] * sv)
                           : (sx[j + 64] * cv + sx[j] * sv);

    if (type == 0) g_q [(m * H_ + slot) * K_ + tid] = out;
    else           g_kn[(m * G_ + gi)  * K_ + tid] = out;
}

// ---------------- K3: split flash attention, tf32 mma, cp.async pipelined ----
// dyn smem floats: QS[2048] | KS[64*132] | VS[64*136] | P[16*68] | M/L/F[48]
#define ATTN_SMEM_FLOATS (2048 + 8448 + 8704 + 1088 + 48)
#define ATTN_SMEM_BYTES  (ATTN_SMEM_FLOATS * 4)

__global__ __launch_bounds__(256, 2) void attn_kernel(
    const float* __restrict__ kc,
    const float* __restrict__ vc,
    const int*   __restrict__ seg,
    const int*   __restrict__ curp)
{
    extern __shared__ float smf[];
    float* QS   = smf;
    float* KS   = smf + 2048;
    float* VS   = KS + 8448;
    float* P    = VS + 8704;
    float* SM_M = P + 1088;
    float* SM_L = SM_M + 16;
    float* SM_F = SM_L + 16;

    int b  = blockIdx.x;
    int g  = blockIdx.y;
    int sp = blockIdx.z;
    int tid  = threadIdx.x;            // 256
    int w    = tid >> 5;
    int lane = tid & 31;
    int gq   = lane >> 2;              // mma group id 0..7
    int tg   = lane & 3;               // thread-in-group 0..3

    int cur   = *curp;
    int s_end = cur + T_;

    int sgv0 = seg[b * T_ + 0], sgv1 = seg[b * T_ + 1];
    int sgv2 = seg[b * T_ + 2], sgv3 = seg[b * T_ + 3];

    // inline left-pads
    int start;
    {
        int csum = 0, lp = 0;
        csum += (sgv0 != 0); if (csum == 0) lp++;
        csum += (sgv1 != 0); if (csum == 0) lp++;
        csum += (sgv2 != 0); if (csum == 0) lp++;
        csum += (sgv3 != 0); if (csum == 0) lp++;
        start = lp;
    }

    // chunk range for this split
    int nch  = (s_end + 63) >> 6;
    int per  = (nch + NS - 1) / NS;
    int c_lo = sp * per;
    int c_hi = min(nch, c_lo + per);
    int cst  = max(c_lo, start >> 6);

    uint32_t ksb = (uint32_t)__cvta_generic_to_shared(KS);
    uint32_t vsb = (uint32_t)__cvta_generic_to_shared(VS);

    auto issueK = [&](int ci) {
        int s0c = ci << 6;
        #pragma unroll
        for (int it = 0; it < 8; it++) {
            int idx = tid + (it << 8);
            int row = idx >> 5;
            int c4  = (idx & 31) << 2;
            int s   = s0c + row;
            const float* src; bool p = true;
            if (s < cur)        src = kc + ((((size_t)(b * S_ + s)) * G_ + g) << 7) + c4;
            else if (s < s_end) src = g_kn + (((b * T_ + (s - cur)) * G_ + g) << 7) + c4;
            else              { src = kc; p = false; }
            cp_async16(ksb + (uint32_t)(row * 132 + c4) * 4, src, p);
        }
    };
    auto issueV = [&](int ci) {
        int s0c = ci << 6;
        #pragma unroll
        for (int it = 0; it < 8; it++) {
            int idx = tid + (it << 8);
            int row = idx >> 5;
            int c4  = (idx & 31) << 2;
            int s   = s0c + row;
            const float* src; bool p = true;
            if (s < cur)        src = vc + ((((size_t)(b * S_ + s)) * G_ + g) << 7) + c4;
            else if (s < s_end) src = g_vn + (((b * T_ + (s - cur)) * G_ + g) << 7) + c4;
            else              { src = vc; p = false; }
            cp_async16(vsb + (uint32_t)(row * 136 + c4) * 4, src, p);
        }
    };

    // prologue: stage first chunk (K group, then V group)
    if (cst < c_hi) { issueK(cst); cp_commit(); issueV(cst); cp_commit(); }

    // stage the 16 query vectors into QS (overlaps with cp.async)
    #pragma unroll
    for (int it = 0; it < 2; it++) {
        int idx = tid + (it << 8);
        int q   = idx >> 5;
        int c4  = (idx & 31) << 2;
        int t = q >> 2, rr = q & 3;
        float4 qv = *(const float4*)(g_q + (((b * T_ + t) * H_ + (g * NREP + rr)) << 7) + c4);
        *(float4*)(QS + q * 128 + c4) = qv;
    }
    if (tid < 16) { SM_M[tid] = -3e38f; SM_L[tid] = 0.f; }
    __syncthreads();

    // convert Q fragments to tf32 registers once
    uint32_t qa[16][4];
    #pragma unroll
    for (int ks = 0; ks < 16; ks++) {
        int col = (ks << 3) + tg;
        qa[ks][0] = cvt_tf32(QS[ gq      * 128 + col]);
        qa[ks][1] = cvt_tf32(QS[(gq + 8) * 128 + col]);
        qa[ks][2] = cvt_tf32(QS[ gq      * 128 + col + 4]);
        qa[ks][3] = cvt_tf32(QS[(gq + 8) * 128 + col + 4]);
    }

    // PV accumulators: warp w owns dims [16w, 16w+16), all 16 queries
    float oc[2][4];
    #pragma unroll
    for (int t = 0; t < 2; t++)
        #pragma unroll
        for (int j = 0; j < 4; j++) oc[t][j] = 0.f;

    int n0 = w << 3;                    // logits: this warp's 8 keys

    for (int ci = cst; ci < c_hi; ci++) {
        int s0 = ci << 6;
        cp_wait<1>();                   // K(ci) complete (V(ci) may be pending)
        __syncthreads();

        // ---- logits: warp computes 16 queries x its 8 keys via mma ----
        {
            float sc_[4] = {0.f, 0.f, 0.f, 0.f};
            #pragma unroll
            for (int ks = 0; ks < 16; ks++) {
                int col = (ks << 3) + tg;
                uint32_t b0 = cvt_tf32(KS[(n0 + gq) * 132 + col]);
                uint32_t b1 = cvt_tf32(KS[(n0 + gq) * 132 + col + 4]);
                mma_tf32(sc_, qa[ks][0], qa[ks][1], qa[ks][2], qa[ks][3], b0, b1);
            }
            int sl0 = n0 + (tg << 1);
            int sgl0 = s0 + sl0, sgl1 = sgl0 + 1;
            int kv0 = (sgl0 >= start && sgl0 < s_end) ? 1 : 0;
            int kv1 = (sgl1 >= start && sgl1 < s_end) ? 1 : 0;
            int sgv[4] = {sgv0, sgv1, sgv2, sgv3};
            int t0 = gq >> 2, t1 = (gq + 8) >> 2;
            bool ok00 = (sgl0 <= cur + t0) && (kv0 == sgv[t0]);
            bool ok01 = (sgl1 <= cur + t0) && (kv1 == sgv[t0]);
            bool ok10 = (sgl0 <= cur + t1) && (kv0 == sgv[t1]);
            bool ok11 = (sgl1 <= cur + t1) && (kv1 == sgv[t1]);
            P[ gq      * 68 + sl0    ] = ok00 ? sc_[0] * SCALE_ : -3e38f;
            P[ gq      * 68 + sl0 + 1] = ok01 ? sc_[1] * SCALE_ : -3e38f;
            P[(gq + 8) * 68 + sl0    ] = ok10 ? sc_[2] * SCALE_ : -3e38f;
            P[(gq + 8) * 68 + sl0 + 1] = ok11 ? sc_[3] * SCALE_ : -3e38f;
        }
        __syncthreads();                // P written, KS fully consumed

        if (ci + 1 < c_hi) issueK(ci + 1);
        cp_commit();                    // overlaps softmax + PV

        // ---- online softmax: warp w owns queries {2w, 2w+1} ----
        #pragma unroll
        for (int j = 0; j < 2; j++) {
            int q = (w << 1) + j;
            float v0 = P[q * 68 + lane];
            float v1 = P[q * 68 + lane + 32];
            float cm = fmaxf(v0, v1);
            #pragma unroll
            for (int o = 16; o; o >>= 1) cm = fmaxf(cm, __shfl_xor_sync(0xffffffffu, cm, o));
            float mold = SM_M[q];
            float mnew = fmaxf(mold, cm);
            float e0 = (v0 < -1e37f) ? 0.f : __expf(v0 - mnew);
            float e1 = (v1 < -1e37f) ? 0.f : __expf(v1 - mnew);
            P[q * 68 + lane]      = e0;
            P[q * 68 + lane + 32] = e1;
            float sum = e0 + e1;
            #pragma unroll
            for (int o = 16; o; o >>= 1) sum += __shfl_xor_sync(0xffffffffu, sum, o);
            if (lane == 0) {
                float f = (mold < -1e37f) ? 0.f : __expf(mold - mnew);
                SM_F[q] = f;
                SM_L[q] = SM_L[q] * f + sum;
                SM_M[q] = mnew;
            }
        }
        cp_wait<1>();                   // V(ci) complete (K(ci+1) pending)
        __syncthreads();                // exp P + SM_F visible, VS ready

        // ---- PV: warp w, dims 16w..16w+15, all queries, via mma ----
        {
            float f0 = SM_F[gq], f1 = SM_F[gq + 8];
            #pragma unroll
            for (int t = 0; t < 2; t++) {
                oc[t][0] *= f0; oc[t][1] *= f0;
                oc[t][2] *= f1; oc[t][3] *= f1;
            }
            #pragma unroll
            for (int ks = 0; ks < 8; ks++) {
                int kr = (ks << 3) + tg;
                uint32_t a0 = cvt_tf32(P[ gq      * 68 + kr]);
                uint32_t a1 = cvt_tf32(P[(gq + 8) * 68 + kr]);
                uint32_t a2 = cvt_tf32(P[ gq      * 68 + kr + 4]);
                uint32_t a3 = cvt_tf32(P[(gq + 8) * 68 + kr + 4]);
                #pragma unroll
                for (int t = 0; t < 2; t++) {
                    int nd = (w << 4) + (t << 3) + gq;
                    uint32_t b0 = cvt_tf32(VS[kr * 136 + nd]);
                    uint32_t b1 = cvt_tf32(VS[(kr + 4) * 136 + nd]);
                    mma_tf32(oc[t], a0, a1, a2, a3, b0, b1);
                }
            }
        }
        __syncthreads();                // VS fully consumed

        if (ci + 1 < c_hi) issueV(ci + 1);
        cp_commit();                    // overlaps next logits
    }

    // ---- write partials (unnormalized) ----
    {
        int pbase = ((b * G_ + g) * NS + sp) * 16;
        #pragma unroll
        for (int t = 0; t < 2; t++) {
            int col = (w << 4) + (t << 3) + (tg << 1);
            *(float2*)(g_pacc + (size_t)(pbase + gq) * 128 + col)
                = make_float2(oc[t][0], oc[t][1]);
            *(float2*)(g_pacc + (size_t)(pbase + gq + 8) * 128 + col)
                = make_float2(oc[t][2], oc[t][3]);
        }
        if (tid < 16) {
            g_pm[pbase + tid] = SM_M[tid];
            g_pl[pbase + tid] = SM_L[tid];
        }
    }
}

// ---------------- K3b: combine split partials ----------------
__global__ void combine_kernel() {
    int bg  = blockIdx.x;              // 0..127 = b*G+g
    int tid = threadIdx.x;             // 256
    int q   = tid >> 4;                // 0..15
    int kb  = (tid & 15) << 3;         // 8 dims
    int base = bg * NS * 16;

    float m = -3e38f;
    #pragma unroll
    for (int s = 0; s < NS; s++) m = fmaxf(m, g_pm[base + s * 16 + q]);

    float lsum = 0.f;
    float o[8];
    #pragma unroll
    for (int j = 0; j < 8; j++) o[j] = 0.f;

    #pragma unroll
    for (int s = 0; s < NS; s++) {
        float ms  = g_pm[base + s * 16 + q];
        float wgt = (ms < -1e37f) ? 0.f : __expf(ms - m);
        lsum += wgt * g_pl[base + s * 16 + q];
        const float* pa = g_pacc + (size_t)(base + s * 16 + q) * 128 + kb;
        float4 x0 = *(const float4*)pa;
        float4 x1 = *(const float4*)(pa + 4);
        o[0] = fmaf(wgt, x0.x, o[0]); o[1] = fmaf(wgt, x0.y, o[1]);
        o[2] = fmaf(wgt, x0.z, o[2]); o[3] = fmaf(wgt, x0.w, o[3]);
        o[4] = fmaf(wgt, x1.x, o[4]); o[5] = fmaf(wgt, x1.y, o[5]);
        o[6] = fmaf(wgt, x1.z, o[6]); o[7] = fmaf(wgt, x1.w, o[7]);
    }
    float inv = (lsum > 0.f) ? (1.0f / lsum) : 0.f;
    int b = bg >> 2, g = bg & 3;
    int t = q >> 2, r = q & 3;
    float* dst = g_attn + (((b * T_ + t) * H_ + g * NREP + r) << 7) + kb;
    *(float4*)dst       = make_float4(o[0]*inv, o[1]*inv, o[2]*inv, o[3]*inv);
    *(float4*)(dst + 4) = make_float4(o[4]*inv, o[5]*inv, o[6]*inv, o[7]*inv);
}

// ---------------- host launch ----------------
extern "C" void kernel_launch(void* const* d_in, const int* in_sizes, int n_in,
                              void* d_out, int out_size) {
    const float* hidden = (const float*)d_in[0];
    const int*   seg    = (const int*)  d_in[1];
    const float* kc     = (const float*)d_in[2];
    const float* vc     = (const float*)d_in[3];
    const float* Wq     = (const float*)d_in[4];
    const float* Wk     = (const float*)d_in[5];
    const float* Wv     = (const float*)d_in[6];
    const float* Wo     = (const float*)d_in[7];
    const float* qsc    = (const float*)d_in[8];
    const float* ksc    = (const float*)d_in[9];
    const int*   curp   = (const int*)  d_in[10];

    (void)in_sizes; (void)n_in; (void)out_size;

    mma_gemm_kernel<64><<<dim3(48, 2, 2), 128>>>(hidden, Wq, Wk, Wv, 3072, 1);
    normrope_kernel<<<dim3(24, 128), 128>>>(qsc, ksc, seg, curp);
    cudaFuncSetAttribute(attn_kernel, cudaFuncAttributeMaxDynamicSharedMemorySize,
                         ATTN_SMEM_BYTES);
    attn_kernel<<<dim3(B_, G_, NS), 256, ATTN_SMEM_BYTES>>>(kc, vc, seg, curp);
    combine_kernel<<<128, 256>>>();
    mma_gemm_kernel<32><<<dim3(32, 2, 4), 128>>>(nullptr, Wo, Wo, Wo, 2048, 0);
    wo_reduce_kernel<<<256, 256>>>((float*)d_out);
}

// round 15
// speedup vs baseline: 4.4470x; 1.0725x over previous
#include <cuda_runtime.h>
#include <cuda_bf16.h>
#include <stdint.h>
#include <stddef.h>

// Problem constants
#define B_   32
#define T_   4
#define D_   2048
#define H_   16
#define G_   4
#define K_   128
#define S_   4096
#define NREP 4
#define NS   7            // sequence splits for attention (49 chunks / 7 = balanced)
#define SCALE_ 0.08838834764831845f   // K^-0.5
#define EPS_   1e-6f

// ---------------- device scratch (no allocations allowed) ----------------
__device__ __align__(16) float g_qkvp[4 * 128 * 3072];  // QKV split-K partials
__device__ __align__(16) float g_wop [8 * 128 * 2048];  // Wo split-K partials
__device__ __align__(16) float g_q  [128 * H_ * K_];    // post norm+rope
__device__ __align__(16) float g_kn [128 * G_ * K_];    // new K rows
__device__ __align__(16) float g_vn [128 * G_ * K_];    // new V rows
__device__ __align__(16) float g_attn[128 * H_ * K_];   // attention out
// split-attention partials
__device__ __align__(16) float g_pacc[B_ * G_ * NS * 16 * 128];
__device__ float g_pm  [B_ * G_ * NS * 16];
__device__ float g_pl  [B_ * G_ * NS * 16];

// ---------------- cp.async helpers ----------------
__device__ __forceinline__ void cp_async16(uint32_t dst, const void* src, bool p) {
    asm volatile("cp.async.cg.shared.global [%0], [%1], 16, %2;\n"
                 :: "r"(dst), "l"(src), "r"(p ? 16 : 0));
}
__device__ __forceinline__ void cp_commit() {
    asm volatile("cp.async.commit_group;\n" ::);
}
template<int N> __device__ __forceinline__ void cp_wait() {
    asm volatile("cp.async.wait_group %0;\n" :: "n"(N));
}

// ---------------- tf32 mma helpers ----------------
__device__ __forceinline__ uint32_t cvt_tf32(float x) {
    uint32_t u;
    asm("cvt.rna.tf32.f32 %0, %1;" : "=r"(u) : "f"(x));
    return u;
}
__device__ __forceinline__ void mma_tf32(float c[4],
    uint32_t a0, uint32_t a1, uint32_t a2, uint32_t a3,
    uint32_t b0, uint32_t b1)
{
    asm volatile(
        "mma.sync.aligned.m16n8k8.row.col.f32.tf32.tf32.f32 "
        "{%0,%1,%2,%3}, {%4,%5,%6,%7}, {%8,%9}, {%0,%1,%2,%3};\n"
        : "+f"(c[0]), "+f"(c[1]), "+f"(c[2]), "+f"(c[3])
        : "r"(a0), "r"(a1), "r"(a2), "r"(a3), "r"(b0), "r"(b1));
}

// ---------------- GEMM: tf32 mma, 64x64 tile, split-K via blockIdx.z ---------
template<int KIT>
__global__ __launch_bounds__(128) void mma_gemm_kernel(
    const float* __restrict__ A_,
    const float* __restrict__ W0, const float* __restrict__ W1,
    const float* __restrict__ W2,
    int ldc, int qkv)
{
    __shared__ alignas(16) float As[4][64][20];   // [buf][m][k], stride 20
    __shared__ alignas(16) float Ws[4][16][72];   // [buf][k][n], stride 72

    const float* A = qkv ? A_ : (const float*)g_attn;
    float*       C = qkv ? (g_qkvp + (size_t)blockIdx.z * 128 * 3072)
                         : (g_wop  + (size_t)blockIdx.z * 128 * 2048);
    int kbase = blockIdx.z * KIT;

    int c0 = blockIdx.x * 64;
    const float* W; int ldb, cb;
    if (qkv) {
        if (c0 < 2048)      { W = W0; ldb = 2048; cb = c0; }
        else if (c0 < 2560) { W = W1; ldb = 512;  cb = c0 - 2048; }
        else                { W = W2; ldb = 512;  cb = c0 - 2560; }
    } else                  { W = W0; ldb = 2048; cb = c0; }

    int m0   = blockIdx.y * 64;
    int tid  = threadIdx.x;           // 128
    int wid  = tid >> 5;
    int lane = tid & 31;
    int gq   = lane >> 2;             // group id 0..7
    int tg   = lane & 3;              // thread-in-group 0..3
    int wm0  = (wid >> 1) << 5;       // warp m offset 0/32
    int wn0  = (wid & 1) << 5;        // warp n offset 0/32

    uint32_t sAs = (uint32_t)__cvta_generic_to_shared(&As[0][0][0]);
    uint32_t sWs = (uint32_t)__cvta_generic_to_shared(&Ws[0][0][0]);

    auto issue = [&](int it, int buf) {
        int k0 = (kbase + it) << 4;
        #pragma unroll
        for (int j = 0; j < 2; j++) {                // A: 64 rows x 16 cols
            int idx = tid + (j << 7);                // 0..255 float4
            int row = idx >> 2, q = (idx & 3) << 2;
            cp_async16(sAs + (uint32_t)(buf * 1280 + row * 20 + q) * 4,
                       A + (size_t)(m0 + row) * 2048 + k0 + q, true);
        }
        #pragma unroll
        for (int j = 0; j < 2; j++) {                // W: 16 rows x 64 cols
            int idx = tid + (j << 7);                // 0..255 float4
            int row = idx >> 4, q = (idx & 15) << 2;
            cp_async16(sWs + (uint32_t)(buf * 1152 + row * 72 + q) * 4,
                       W + (size_t)(k0 + row) * ldb + cb + q, true);
        }
    };

    float c[2][4][4];
    #pragma unroll
    for (int mb = 0; mb < 2; mb++)
        #pragma unroll
        for (int nb = 0; nb < 4; nb++)
            #pragma unroll
            for (int j = 0; j < 4; j++) c[mb][nb][j] = 0.f;

    issue(0, 0); cp_commit();
    issue(1, 1); cp_commit();
    issue(2, 2); cp_commit();

    for (int it = 0; it < KIT; it++) {
        int bf = it & 3;
        cp_wait<2>();
        __syncthreads();

        #pragma unroll
        for (int kk = 0; kk < 16; kk += 8) {
            uint32_t a[2][4], bfr[4][2];
            #pragma unroll
            for (int mb = 0; mb < 2; mb++) {
                int r0 = wm0 + (mb << 4) + gq;
                a[mb][0] = cvt_tf32(As[bf][r0    ][kk + tg]);
                a[mb][1] = cvt_tf32(As[bf][r0 + 8][kk + tg]);
                a[mb][2] = cvt_tf32(As[bf][r0    ][kk + tg + 4]);
                a[mb][3] = cvt_tf32(As[bf][r0 + 8][kk + tg + 4]);
            }
            #pragma unroll
            for (int nb = 0; nb < 4; nb++) {
                int cn = wn0 + (nb << 3) + gq;
                bfr[nb][0] = cvt_tf32(Ws[bf][kk + tg    ][cn]);
                bfr[nb][1] = cvt_tf32(Ws[bf][kk + tg + 4][cn]);
            }
            #pragma unroll
            for (int mb = 0; mb < 2; mb++)
                #pragma unroll
                for (int nb = 0; nb < 4; nb++)
                    mma_tf32(c[mb][nb], a[mb][0], a[mb][1], a[mb][2], a[mb][3],
                             bfr[nb][0], bfr[nb][1]);
        }
        __syncthreads();
        if (it + 3 < KIT) issue(it + 3, (it + 3) & 3);
        cp_commit();
    }

    #pragma unroll
    for (int mb = 0; mb < 2; mb++)
        #pragma unroll
        for (int nb = 0; nb < 4; nb++) {
            int row = m0 + wm0 + (mb << 4) + gq;
            int col = c0 + wn0 + (nb << 3) + (tg << 1);
            *(float2*)(C + (size_t)row * ldc + col)
                = make_float2(c[mb][nb][0], c[mb][nb][1]);
            *(float2*)(C + (size_t)(row + 8) * ldc + col)
                = make_float2(c[mb][nb][2], c[mb][nb][3]);
        }
}

// ---------------- Wo split-K reduce: d_out = sum of 8 partials ----------------
__global__ void wo_reduce_kernel(float* __restrict__ out) {
    int idx = (blockIdx.x * 256 + threadIdx.x) << 2;   // float4 index space
    float4 s = *(const float4*)(g_wop + idx);
    #pragma unroll
    for (int z = 1; z < 8; z++) {
        float4 a = *(const float4*)(g_wop + (size_t)z * 262144 + idx);
        s.x += a.x; s.y += a.y; s.z += a.z; s.w += a.w;
    }
    *(float4*)(out + idx) = s;
}

// ---------------- K2: rmsnorm + rope + split (sums QKV split-K partials) -----
__global__ void normrope_kernel(const float* __restrict__ q_scale,
                                const float* __restrict__ k_scale,
                                const int*   __restrict__ seg,
                                const int*   __restrict__ curp)
{
    int slot = blockIdx.x;
    int m    = blockIdx.y;
    int tid  = threadIdx.x;

    int cbase, type, gi = 0;
    if (slot < 16)      { cbase = slot * 128;               type = 0; }
    else if (slot < 20) { cbase = 2048 + (slot - 16) * 128; type = 1; gi = slot - 16; }
    else                { cbase = 2560 + (slot - 20) * 128; type = 2; gi = slot - 20; }

    int idx = m * 3072 + cbase + tid;
    float x = g_qkvp[idx] + g_qkvp[393216 + idx]
            + g_qkvp[786432 + idx] + g_qkvp[1179648 + idx];

    if (type == 2) {   // V: no norm, no rope
        g_vn[(m * G_ + gi) * K_ + tid] = x;
        return;
    }

    __shared__ float wsum[4];
    __shared__ float sx[128];

    float ss = x * x;
    #pragma unroll
    for (int o = 16; o; o >>= 1) ss += __shfl_xor_sync(0xffffffffu, ss, o);
    if ((tid & 31) == 0) wsum[tid >> 5] = ss;
    __syncthreads();
    float var = (wsum[0] + wsum[1] + wsum[2] + wsum[3]) * (1.0f / 128.0f);

    float sc = (type == 0) ? q_scale[tid] : k_scale[tid];
    float xn = x * rsqrtf(var + EPS_) * sc;
    sx[tid] = xn;
    __syncthreads();

    int bb = m >> 2, tt = m & 3;
    int csum = 0;
    #pragma unroll
    for (int t = 0; t < T_; t++)
        if (t <= tt) csum += (seg[bb * T_ + t] != 0) ? 1 : 0;
    int pos = csum - 1 + *curp;

    int   j   = tid & 63;
    float fr  = (float)j * (1.0f / 64.0f);
    float ts  = powf(10000.0f, fr);        // accurate pow (large angles)
    float ang = (float)pos / ts;
    float sv, cv;
    sincosf(ang, &sv, &cv);

    float out = (tid < 64) ? (sx[j] * cv - sx[j + 64] * sv)
                           : (sx[j + 64] * cv + sx[j] * sv);

    if (type == 0) g_q [(m * H_ + slot) * K_ + tid] = out;
    else           g_kn[(m * G_ + gi)  * K_ + tid] = out;
}

// ---------------- K3: split flash attention, tf32 mma, deep pipeline ---------
// dyn smem floats: KS[2][64*132] | VS[64*136] | P[16*68] | M/L/F[48]
#define ATTN_SMEM_FLOATS (16896 + 8704 + 1088 + 48)
#define ATTN_SMEM_BYTES  (ATTN_SMEM_FLOATS * 4)

__global__ __launch_bounds__(256, 2) void attn_kernel(
    const float* __restrict__ kc,
    const float* __restrict__ vc,
    const int*   __restrict__ seg,
    const int*   __restrict__ curp)
{
    extern __shared__ float smf[];
    float* KS0  = smf;                 // KS[buf] = smf + buf*8448
    float* VS   = smf + 16896;
    float* P    = VS + 8704;
    float* SM_M = P + 1088;
    float* SM_L = SM_M + 16;
    float* SM_F = SM_L + 16;

    int b  = blockIdx.x;
    int g  = blockIdx.y;
    int sp = blockIdx.z;
    int tid  = threadIdx.x;            // 256
    int w    = tid >> 5;
    int lane = tid & 31;
    int gq   = lane >> 2;              // mma group id 0..7
    int tg   = lane & 3;               // thread-in-group 0..3

    int cur   = *curp;
    int s_end = cur + T_;

    int sgv0 = seg[b * T_ + 0], sgv1 = seg[b * T_ + 1];
    int sgv2 = seg[b * T_ + 2], sgv3 = seg[b * T_ + 3];

    // inline left-pads
    int start;
    {
        int csum = 0, lp = 0;
        csum += (sgv0 != 0); if (csum == 0) lp++;
        csum += (sgv1 != 0); if (csum == 0) lp++;
        csum += (sgv2 != 0); if (csum == 0) lp++;
        csum += (sgv3 != 0); if (csum == 0) lp++;
        start = lp;
    }

    // chunk range for this split
    int nch  = (s_end + 63) >> 6;
    int per  = (nch + NS - 1) / NS;
    int c_lo = sp * per;
    int c_hi = min(nch, c_lo + per);
    int cst  = max(c_lo, start >> 6);

    uint32_t ksb = (uint32_t)__cvta_generic_to_shared(KS0);
    uint32_t vsb = (uint32_t)__cvta_generic_to_shared(VS);

    auto issueK = [&](int ci) {
        int s0c = ci << 6;
        uint32_t base = ksb + (uint32_t)(ci & 1) * 8448 * 4;
        #pragma unroll
        for (int it = 0; it < 8; it++) {
            int idx = tid + (it << 8);
            int row = idx >> 5;
            int c4  = (idx & 31) << 2;
            int s   = s0c + row;
            const float* src; bool p = true;
            if (s < cur)        src = kc + ((((size_t)(b * S_ + s)) * G_ + g) << 7) + c4;
            else if (s < s_end) src = g_kn + (((b * T_ + (s - cur)) * G_ + g) << 7) + c4;
            else              { src = kc; p = false; }
            cp_async16(base + (uint32_t)(row * 132 + c4) * 4, src, p);
        }
    };
    auto issueV = [&](int ci) {
        int s0c = ci << 6;
        #pragma unroll
        for (int it = 0; it < 8; it++) {
            int idx = tid + (it << 8);
            int row = idx >> 5;
            int c4  = (idx & 31) << 2;
            int s   = s0c + row;
            const float* src; bool p = true;
            if (s < cur)        src = vc + ((((size_t)(b * S_ + s)) * G_ + g) << 7) + c4;
            else if (s < s_end) src = g_vn + (((b * T_ + (s - cur)) * G_ + g) << 7) + c4;
            else              { src = vc; p = false; }
            cp_async16(vsb + (uint32_t)(row * 136 + c4) * 4, src, p);
        }
    };

    // prologue: pending order must be [K(cst), K(cst+1), V(cst)]
    if (cst < c_hi)     issueK(cst);     cp_commit();
    if (cst + 1 < c_hi) issueK(cst + 1); cp_commit();
    if (cst < c_hi)     issueV(cst);     cp_commit();

    if (tid < 16) { SM_M[tid] = -3e38f; SM_L[tid] = 0.f; }

    // convert Q fragments to tf32 registers once (direct from gmem; no QS)
    uint32_t qa[16][4];
    {
        int q0i = gq, q1i = gq + 8;
        const float* qp0 = g_q + (((b * T_ + (q0i >> 2)) * H_ + g * NREP + (q0i & 3)) << 7);
        const float* qp1 = g_q + (((b * T_ + (q1i >> 2)) * H_ + g * NREP + (q1i & 3)) << 7);
        #pragma unroll
        for (int ks = 0; ks < 16; ks++) {
            int col = (ks << 3) + tg;
            qa[ks][0] = cvt_tf32(__ldg(qp0 + col));
            qa[ks][1] = cvt_tf32(__ldg(qp1 + col));
            qa[ks][2] = cvt_tf32(__ldg(qp0 + col + 4));
            qa[ks][3] = cvt_tf32(__ldg(qp1 + col + 4));
        }
    }

    // PV accumulators: warp w owns dims [16w, 16w+16), all 16 queries
    float oc[2][4];
    #pragma unroll
    for (int t = 0; t < 2; t++)
        #pragma unroll
        for (int j = 0; j < 4; j++) oc[t][j] = 0.f;

    int n0 = w << 3;                    // logits: this warp's 8 keys
    __syncthreads();                    // SM_M/SM_L visible

    for (int ci = cst; ci < c_hi; ci++) {
        int s0 = ci << 6;
        // pending: [K(ci), K(ci+1), V(ci)]
        cp_wait<2>();                   // K(ci) complete
        __syncthreads();

        // ---- logits: warp computes 16 queries x its 8 keys via mma ----
        {
            const float* KS = KS0 + (ci & 1) * 8448;
            float sc_[4] = {0.f, 0.f, 0.f, 0.f};
            #pragma unroll
            for (int ks = 0; ks < 16; ks++) {
                int col = (ks << 3) + tg;
                uint32_t b0 = cvt_tf32(KS[(n0 + gq) * 132 + col]);
                uint32_t b1 = cvt_tf32(KS[(n0 + gq) * 132 + col + 4]);
                mma_tf32(sc_, qa[ks][0], qa[ks][1], qa[ks][2], qa[ks][3], b0, b1);
            }
            int sl0 = n0 + (tg << 1);
            int sgl0 = s0 + sl0, sgl1 = sgl0 + 1;
            int kv0 = (sgl0 >= start && sgl0 < s_end) ? 1 : 0;
            int kv1 = (sgl1 >= start && sgl1 < s_end) ? 1 : 0;
            int sgv[4] = {sgv0, sgv1, sgv2, sgv3};
            int t0 = gq >> 2, t1 = (gq + 8) >> 2;
            bool ok00 = (sgl0 <= cur + t0) && (kv0 == sgv[t0]);
            bool ok01 = (sgl1 <= cur + t0) && (kv1 == sgv[t0]);
            bool ok10 = (sgl0 <= cur + t1) && (kv0 == sgv[t1]);
            bool ok11 = (sgl1 <= cur + t1) && (kv1 == sgv[t1]);
            P[ gq      * 68 + sl0    ] = ok00 ? sc_[0] * SCALE_ : -3e38f;
            P[ gq      * 68 + sl0 + 1] = ok01 ? sc_[1] * SCALE_ : -3e38f;
            P[(gq + 8) * 68 + sl0    ] = ok10 ? sc_[2] * SCALE_ : -3e38f;
            P[(gq + 8) * 68 + sl0 + 1] = ok11 ? sc_[3] * SCALE_ : -3e38f;
        }
        __syncthreads();                // P written, KS[ci&1] fully consumed

        if (ci + 2 < c_hi) issueK(ci + 2);   // reuses KS[ci&1], now free
        cp_commit();                    // pending: [K(ci+1), V(ci), K(ci+2)]

        // ---- online softmax: warp w owns queries {2w, 2w+1} ----
        #pragma unroll
        for (int j = 0; j < 2; j++) {
            int q = (w << 1) + j;
            float v0 = P[q * 68 + lane];
            float v1 = P[q * 68 + lane + 32];
            float cm = fmaxf(v0, v1);
            #pragma unroll
            for (int o = 16; o; o >>= 1) cm = fmaxf(cm, __shfl_xor_sync(0xffffffffu, cm, o));
            float mold = SM_M[q];
            float mnew = fmaxf(mold, cm);
            float e0 = (v0 < -1e37f) ? 0.f : __expf(v0 - mnew);
            float e1 = (v1 < -1e37f) ? 0.f : __expf(v1 - mnew);
            P[q * 68 + lane]      = e0;
            P[q * 68 + lane + 32] = e1;
            float sum = e0 + e1;
            #pragma unroll
            for (int o = 16; o; o >>= 1) sum += __shfl_xor_sync(0xffffffffu, sum, o);
            if (lane == 0) {
                float f = (mold < -1e37f) ? 0.f : __expf(mold - mnew);
                SM_F[q] = f;
                SM_L[q] = SM_L[q] * f + sum;
                SM_M[q] = mnew;
            }
        }
        cp_wait<1>();                   // V(ci) complete (K(ci+2) may pend)
        __syncthreads();                // exp P + SM_F visible, VS ready

        // ---- PV: warp w, dims 16w..16w+15, all queries, via mma ----
        {
            float f0 = SM_F[gq], f1 = SM_F[gq + 8];
            #pragma unroll
            for (int t = 0; t < 2; t++) {
                oc[t][0] *= f0; oc[t][1] *= f0;
                oc[t][2] *= f1; oc[t][3] *= f1;
            }
            #pragma unroll
            for (int ks = 0; ks < 8; ks++) {
                int kr = (ks << 3) + tg;
                uint32_t a0 = cvt_tf32(P[ gq      * 68 + kr]);
                uint32_t a1 = cvt_tf32(P[(gq + 8) * 68 + kr]);
                uint32_t a2 = cvt_tf32(P[ gq      * 68 + kr + 4]);
                uint32_t a3 = cvt_tf32(P[(gq + 8) * 68 + kr + 4]);
                #pragma unroll
                for (int t = 0; t < 2; t++) {
                    int nd = (w << 4) + (t << 3) + gq;
                    uint32_t b0 = cvt_tf32(VS[kr * 136 + nd]);
                    uint32_t b1 = cvt_tf32(VS[(kr + 4) * 136 + nd]);
                    mma_tf32(oc[t], a0, a1, a2, a3, b0, b1);
                }
            }
        }
        __syncthreads();                // VS fully consumed

        if (ci + 1 < c_hi) issueV(ci + 1);
        cp_commit();                    // pending: [K(ci+1), K(ci+2), V(ci+1)]
    }

    cp_wait<0>();                       // drain any empty tail groups

    // ---- write partials (unnormalized) ----
    {
        int pbase = ((b * G_ + g) * NS + sp) * 16;
        #pragma unroll
        for (int t = 0; t < 2; t++) {
            int col = (w << 4) + (t << 3) + (tg << 1);
            *(float2*)(g_pacc + (size_t)(pbase + gq) * 128 + col)
                = make_float2(oc[t][0], oc[t][1]);
            *(float2*)(g_pacc + (size_t)(pbase + gq + 8) * 128 + col)
                = make_float2(oc[t][2], oc[t][3]);
        }
        if (tid < 16) {
            g_pm[pbase + tid] = SM_M[tid];
            g_pl[pbase + tid] = SM_L[tid];
        }
    }
}

// ---------------- K3b: combine split partials (256 CTAs) ----------------
__global__ void combine_kernel() {
    int bg   = blockIdx.x;             // 0..127 = b*G+g
    int half = blockIdx.y;             // 0/1: which 64 dims
    int tid  = threadIdx.x;            // 256
    int q    = tid >> 4;               // 0..15
    int kb   = ((tid & 15) << 2) + (half << 6);   // 4 dims per thread
    int base = bg * NS * 16;

    float m = -3e38f;
    #pragma unroll
    for (int s = 0; s < NS; s++) m = fmaxf(m, g_pm[base + s * 16 + q]);

    float lsum = 0.f;
    float4 o = make_float4(0.f, 0.f, 0.f, 0.f);

    #pragma unroll
    for (int s = 0; s < NS; s++) {
        float ms  = g_pm[base + s * 16 + q];
        float wgt = (ms < -1e37f) ? 0.f : __expf(ms - m);
        lsum += wgt * g_pl[base + s * 16 + q];
        float4 x = *(const float4*)(g_pacc + (size_t)(base + s * 16 + q) * 128 + kb);
        o.x = fmaf(wgt, x.x, o.x); o.y = fmaf(wgt, x.y, o.y);
        o.z = fmaf(wgt, x.z, o.z); o.w = fmaf(wgt, x.w, o.w);
    }
    float inv = (lsum > 0.f) ? (1.0f / lsum) : 0.f;
    int b = bg >> 2, g = bg & 3;
    int t = q >> 2, r = q & 3;
    float* dst = g_attn + (((b * T_ + t) * H_ + g * NREP + r) << 7) + kb;
    *(float4*)dst = make_float4(o.x * inv, o.y * inv, o.z * inv, o.w * inv);
}

// ---------------- host launch ----------------
extern "C" void kernel_launch(void* const* d_in, const int* in_sizes, int n_in,
                              void* d_out, int out_size) {
    const float* hidden = (const float*)d_in[0];
    const int*   seg    = (const int*)  d_in[1];
    const float* kc     = (const float*)d_in[2];
    const float* vc     = (const float*)d_in[3];
    const float* Wq     = (const float*)d_in[4];
    const float* Wk     = (const float*)d_in[5];
    const float* Wv     = (const float*)d_in[6];
    const float* Wo     = (const float*)d_in[7];
    const float* qsc    = (const float*)d_in[8];
    const float* ksc    = (const float*)d_in[9];
    const int*   curp   = (const int*)  d_in[10];

    (void)in_sizes; (void)n_in; (void)out_size;

    mma_gemm_kernel<32><<<dim3(48, 2, 4), 128>>>(hidden, Wq, Wk, Wv, 3072, 1);
    normrope_kernel<<<dim3(24, 128), 128>>>(qsc, ksc, seg, curp);
    cudaFuncSetAttribute(attn_kernel, cudaFuncAttributeMaxDynamicSharedMemorySize,
                         ATTN_SMEM_BYTES);
    attn_kernel<<<dim3(B_, G_, NS), 256, ATTN_SMEM_BYTES>>>(kc, vc, seg, curp);
    combine_kernel<<<dim3(128, 2), 256>>>();
    mma_gemm_kernel<16><<<dim3(32, 2, 8), 128>>>(nullptr, Wo, Wo, Wo, 2048, 0);
    wo_reduce_kernel<<<256, 256>>>((float*)d_out);
}